// round 5
// baseline (speedup 1.0000x reference)
#include <cuda_runtime.h>
#include <cstdint>
#include <cstddef>

#define N_USERS 60000
#define N_ITEMS 40000
#define NTOT    100000
#define EMB     64
#define NNZ_C   2560000
#define BATCH   4096
#define NLAYERS 3
#define ELL_CAP 128        // padded slots per row; P(deg>=128) ~ 0 for Poisson(25.6)

// Scratch (__device__ globals; no allocation allowed)
__device__ float  g_ego [(size_t)NTOT * EMB];
__device__ float  g_side[(size_t)NTOT * EMB];
__device__ float  g_outs[4][(size_t)NTOT * EMB];
__device__ float2 g_edges[(size_t)NTOT * ELL_CAP];  // (val, col-as-float-bits), ELL layout
__device__ int    g_deg [NTOT];                     // atomic slot counter == degree

// ---------------------------------------------------------------------------
// 1) masked ego = concat(user_emb * mask_u, item_emb * mask_i)
// ---------------------------------------------------------------------------
__global__ void init_kernel(const float4* __restrict__ ue,
                            const float4* __restrict__ ie,
                            const int* __restrict__ usz,
                            const int* __restrict__ isz,
                            float4* __restrict__ out0)
{
    int i = blockIdx.x * blockDim.x + threadIdx.x;   // NTOT * 16 float4s
    if (i >= NTOT * 16) return;
    int r = i >> 4;
    int q = i & 15;
    int c0 = q * 4;
    float4 v; int sz;
    if (r < N_USERS) { v = ue[i];                              sz = usz[r]; }
    else             { v = ie[(size_t)(r - N_USERS) * 16 + q]; sz = isz[r - N_USERS]; }
    if (c0 + 0 >= sz) v.x = 0.f;
    if (c0 + 1 >= sz) v.y = 0.f;
    if (c0 + 2 >= sz) v.z = 0.f;
    if (c0 + 3 >= sz) v.w = 0.f;
    out0[i] = v;
}

// ---------------------------------------------------------------------------
// 2) ELL scatter: one pass, no histogram/scan. g_deg must be zeroed first.
// ---------------------------------------------------------------------------
__global__ void scatter_kernel(const float4* __restrict__ vals4,
                               const int4*   __restrict__ rows4,
                               const int4*   __restrict__ cols4)
{
    int i = blockIdx.x * blockDim.x + threadIdx.x;   // NNZ/4 threads
    if (i >= NNZ_C / 4) return;
    float4 v = vals4[i];
    int4   r = rows4[i];
    int4   c = cols4[i];

    int p;
    p = atomicAdd(&g_deg[r.x], 1); if (p < ELL_CAP) g_edges[(size_t)r.x * ELL_CAP + p] = make_float2(v.x, __int_as_float(c.x));
    p = atomicAdd(&g_deg[r.y], 1); if (p < ELL_CAP) g_edges[(size_t)r.y * ELL_CAP + p] = make_float2(v.y, __int_as_float(c.y));
    p = atomicAdd(&g_deg[r.z], 1); if (p < ELL_CAP) g_edges[(size_t)r.z * ELL_CAP + p] = make_float2(v.z, __int_as_float(c.z));
    p = atomicAdd(&g_deg[r.w], 1); if (p < ELL_CAP) g_edges[(size_t)r.w * ELL_CAP + p] = make_float2(v.w, __int_as_float(c.w));
}

// ---------------------------------------------------------------------------
// 3) ELL SpMM: 16 lanes per row, register accumulation, plain stores.
//    (at the L2 gather roofline; unchanged)
// ---------------------------------------------------------------------------
__global__ void __launch_bounds__(256) spmm_kernel(const float* __restrict__ ego,
                                                   float* __restrict__ side)
{
    int tid = blockIdx.x * blockDim.x + threadIdx.x;
    int r = tid >> 4;
    if (r >= NTOT) return;
    int l = tid & 15;

    int deg = g_deg[r];
    if (deg > ELL_CAP) deg = ELL_CAP;
    const float2* ep = g_edges + (size_t)r * ELL_CAP;
    const float*  eg = ego + l * 4;

    float4 acc = make_float4(0.f, 0.f, 0.f, 0.f);

    int j = 0;
    for (; j + 8 <= deg; j += 8) {
        float4 e01 = *(const float4*)(ep + j);
        float4 e23 = *(const float4*)(ep + j + 2);
        float4 e45 = *(const float4*)(ep + j + 4);
        float4 e67 = *(const float4*)(ep + j + 6);
        float4 x0 = *(const float4*)(eg + (size_t)__float_as_int(e01.y) * EMB);
        float4 x1 = *(const float4*)(eg + (size_t)__float_as_int(e01.w) * EMB);
        float4 x2 = *(const float4*)(eg + (size_t)__float_as_int(e23.y) * EMB);
        float4 x3 = *(const float4*)(eg + (size_t)__float_as_int(e23.w) * EMB);
        float4 x4 = *(const float4*)(eg + (size_t)__float_as_int(e45.y) * EMB);
        float4 x5 = *(const float4*)(eg + (size_t)__float_as_int(e45.w) * EMB);
        float4 x6 = *(const float4*)(eg + (size_t)__float_as_int(e67.y) * EMB);
        float4 x7 = *(const float4*)(eg + (size_t)__float_as_int(e67.w) * EMB);
        acc.x += e01.x * x0.x; acc.y += e01.x * x0.y; acc.z += e01.x * x0.z; acc.w += e01.x * x0.w;
        acc.x += e01.z * x1.x; acc.y += e01.z * x1.y; acc.z += e01.z * x1.z; acc.w += e01.z * x1.w;
        acc.x += e23.x * x2.x; acc.y += e23.x * x2.y; acc.z += e23.x * x2.z; acc.w += e23.x * x2.w;
        acc.x += e23.z * x3.x; acc.y += e23.z * x3.y; acc.z += e23.z * x3.z; acc.w += e23.z * x3.w;
        acc.x += e45.x * x4.x; acc.y += e45.x * x4.y; acc.z += e45.x * x4.z; acc.w += e45.x * x4.w;
        acc.x += e45.z * x5.x; acc.y += e45.z * x5.y; acc.z += e45.z * x5.z; acc.w += e45.z * x5.w;
        acc.x += e67.x * x6.x; acc.y += e67.x * x6.y; acc.z += e67.x * x6.z; acc.w += e67.x * x6.w;
        acc.x += e67.z * x7.x; acc.y += e67.z * x7.y; acc.z += e67.z * x7.z; acc.w += e67.z * x7.w;
    }
    for (; j + 2 <= deg; j += 2) {
        float4 e01 = *(const float4*)(ep + j);
        float4 x0 = *(const float4*)(eg + (size_t)__float_as_int(e01.y) * EMB);
        float4 x1 = *(const float4*)(eg + (size_t)__float_as_int(e01.w) * EMB);
        acc.x += e01.x * x0.x; acc.y += e01.x * x0.y; acc.z += e01.x * x0.z; acc.w += e01.x * x0.w;
        acc.x += e01.z * x1.x; acc.y += e01.z * x1.y; acc.z += e01.z * x1.z; acc.w += e01.z * x1.w;
    }
    for (; j < deg; ++j) {
        float2 e = ep[j];
        float4 x = *(const float4*)(eg + (size_t)__float_as_int(e.y) * EMB);
        acc.x += e.x * x.x; acc.y += e.x * x.y; acc.z += e.x * x.z; acc.w += e.x * x.w;
    }

    *(float4*)(side + (size_t)r * EMB + l * 4) = acc;
}

// ---------------------------------------------------------------------------
// 4) Fused dense layer v3: wavefront-optimized shared layout.
//    Block: 64 rows x 64 cols, 128 threads; thread tile 4 rows x 8 cols.
//    W stored bank-swizzled (cols >=32 shifted +4 floats) so each per-thread
//    LDS.128 hits all 32 banks once (1 wavefront). A transposed Ash[k][m].
//    Col-pairs free from W float4s; 4 A-dups per k. Last layer skips ego_out.
// ---------------------------------------------------------------------------
__global__ void __launch_bounds__(128, 5) dense_kernel(
    const float* __restrict__ side, const float* __restrict__ ego,
    const float* __restrict__ Wgc,  const float* __restrict__ bgc,
    const float* __restrict__ Wbi,  const float* __restrict__ bbi,
    float* __restrict__ ego_out,    float* __restrict__ norm_out,
    int write_ego)
{
    __shared__ float Ash[64][68];   // transposed A: Ash[k][m]
    __shared__ float Wsw[64][68];   // swizzled W: col c -> c + (c>=32 ? 4 : 0)
    __shared__ float bsh[64];

    int t = threadIdx.x;
    int row0 = blockIdx.x * 64;
    if (t < 64) bsh[t] = bgc[t] + bbi[t];

    int tx = t & 7, ty = t >> 3;          // tx 0..7 (cols), ty 0..15 (rows)
    int c0 = tx * 8, r0 = ty * 4;
    int wc = c0 + (c0 >= 32 ? 4 : 0);     // swizzled base for this thread's 8 cols

    // acc2[r][q]: row r0+r, column pair (c0+2q, c0+2q+1)
    unsigned long long acc2[4][4];
    #pragma unroll
    for (int r = 0; r < 4; ++r)
        #pragma unroll
        for (int q = 0; q < 4; ++q) acc2[r][q] = 0ull;

    #pragma unroll
    for (int half = 0; half < 2; ++half) {
        const float* W = half ? Wbi : Wgc;
        for (int i = t; i < 64 * 64; i += 128) {
            int k = i >> 6, c = i & 63;
            Wsw[k][c + (c >= 32 ? 4 : 0)] = W[i];
        }
        for (int i = t; i < 64 * 64; i += 128) {
            int m = i >> 6, j = i & 63;
            int r = row0 + m;
            float s = 0.f;
            if (r < NTOT) {
                s = side[(size_t)r * 64 + j];
                if (half) s *= ego[(size_t)r * 64 + j];
            }
            Ash[j][m] = s;
        }
        __syncthreads();

        #pragma unroll 8
        for (int k = 0; k < 64; ++k) {
            float4 a  = *(const float4*)&Ash[k][r0];
            float4 w0 = *(const float4*)&Wsw[k][wc];
            float4 w1 = *(const float4*)&Wsw[k][wc + 4];

            unsigned long long ad[4], bp[4];
            asm("mov.b64 %0, {%1,%1};" : "=l"(ad[0]) : "f"(a.x));
            asm("mov.b64 %0, {%1,%1};" : "=l"(ad[1]) : "f"(a.y));
            asm("mov.b64 %0, {%1,%1};" : "=l"(ad[2]) : "f"(a.z));
            asm("mov.b64 %0, {%1,%1};" : "=l"(ad[3]) : "f"(a.w));
            asm("mov.b64 %0, {%1,%2};" : "=l"(bp[0]) : "f"(w0.x), "f"(w0.y));
            asm("mov.b64 %0, {%1,%2};" : "=l"(bp[1]) : "f"(w0.z), "f"(w0.w));
            asm("mov.b64 %0, {%1,%2};" : "=l"(bp[2]) : "f"(w1.x), "f"(w1.y));
            asm("mov.b64 %0, {%1,%2};" : "=l"(bp[3]) : "f"(w1.z), "f"(w1.w));

            #pragma unroll
            for (int r = 0; r < 4; ++r)
                #pragma unroll
                for (int q = 0; q < 4; ++q)
                    asm("fma.rn.f32x2 %0, %1, %2, %0;"
                        : "+l"(acc2[r][q]) : "l"(ad[r]), "l"(bp[q]));
        }
        __syncthreads();
    }

    // Epilogue: bias + leaky relu + row L2-norm (8 tx lanes share each row)
    #pragma unroll
    for (int r = 0; r < 4; ++r) {
        float v[8];
        #pragma unroll
        for (int q = 0; q < 4; ++q)
            asm("mov.b64 {%0,%1}, %2;" : "=f"(v[2*q]), "=f"(v[2*q+1]) : "l"(acc2[r][q]));

        float sq = 0.f;
        #pragma unroll
        for (int c = 0; c < 8; ++c) {
            float x = v[c] + bsh[c0 + c];
            x = (x > 0.f) ? x : 0.2f * x;
            v[c] = x;
            sq += x * x;
        }
        #pragma unroll
        for (int off = 4; off; off >>= 1)
            sq += __shfl_xor_sync(0xffffffffu, sq, off, 8);
        float inv = 1.0f / fmaxf(sqrtf(sq), 1e-12f);

        int row = row0 + r0 + r;
        if (row < NTOT) {
            float4 o0 = make_float4(v[0], v[1], v[2], v[3]);
            float4 o1 = make_float4(v[4], v[5], v[6], v[7]);
            if (write_ego) {
                *(float4*)(ego_out + (size_t)row * 64 + c0)     = o0;
                *(float4*)(ego_out + (size_t)row * 64 + c0 + 4) = o1;
            }
            float4 n0 = make_float4(o0.x * inv, o0.y * inv, o0.z * inv, o0.w * inv);
            float4 n1 = make_float4(o1.x * inv, o1.y * inv, o1.z * inv, o1.w * inv);
            *(float4*)(norm_out + (size_t)row * 64 + c0)     = n0;
            *(float4*)(norm_out + (size_t)row * 64 + c0 + 4) = n1;
        }
    }
}

// ---------------------------------------------------------------------------
// 5) Final gather
// ---------------------------------------------------------------------------
__global__ void gather_kernel(const int* __restrict__ users,
                              const int* __restrict__ pos,
                              const int* __restrict__ neg,
                              float4* __restrict__ out)
{
    int i = blockIdx.x * blockDim.x + threadIdx.x;   // 3 * BATCH * 64 float4s
    if (i >= 3 * BATCH * 64) return;
    int which = i / (BATCH * 64);
    int rem   = i - which * (BATCH * 64);
    int b  = rem >> 6;
    int q  = rem & 63;
    int slice = q >> 4;
    int qq    = q & 15;

    int row;
    if      (which == 0) row = users[b];
    else if (which == 1) row = N_USERS + pos[b];
    else                 row = N_USERS + neg[b];

    const float4* src = (const float4*)&g_outs[slice][0];
    out[i] = src[(size_t)row * 16 + qq];
}

// ---------------------------------------------------------------------------
// Launcher (graph-capturable)
// ---------------------------------------------------------------------------
extern "C" void kernel_launch(void* const* d_in, const int* in_sizes, int n_in,
                              void* d_out, int out_size)
{
    const float* user_emb   = (const float*)d_in[0];
    const float* item_emb   = (const float*)d_in[1];
    const float* W_gc       = (const float*)d_in[2];
    const float* b_gc       = (const float*)d_in[3];
    const float* W_bi       = (const float*)d_in[4];
    const float* b_bi       = (const float*)d_in[5];
    const float* adj_vals   = (const float*)d_in[6];
    const int*   adj_rows   = (const int*)d_in[7];
    const int*   adj_cols   = (const int*)d_in[8];
    const int*   user_sizes = (const int*)d_in[9];
    const int*   item_sizes = (const int*)d_in[10];
    const int*   users      = (const int*)d_in[11];
    const int*   pos_items  = (const int*)d_in[12];
    const int*   neg_items  = (const int*)d_in[13];

    float *ego, *side, *outs;
    int   *deg;
    cudaGetSymbolAddress((void**)&ego,  g_ego);
    cudaGetSymbolAddress((void**)&side, g_side);
    cudaGetSymbolAddress((void**)&outs, g_outs);
    cudaGetSymbolAddress((void**)&deg,  g_deg);

    const size_t SLICE = (size_t)NTOT * EMB;

    init_kernel<<<(NTOT * 16 + 255) / 256, 256>>>(
        (const float4*)user_emb, (const float4*)item_emb,
        user_sizes, item_sizes, (float4*)outs);

    cudaMemsetAsync(deg, 0, NTOT * sizeof(int), 0);
    scatter_kernel<<<(NNZ_C / 4 + 255) / 256, 256>>>(
        (const float4*)adj_vals, (const int4*)adj_rows, (const int4*)adj_cols);

    const float* ego_in = outs;   // g_outs[0]
    for (int k = 0; k < NLAYERS; ++k) {
        spmm_kernel<<<(NTOT * 16 + 255) / 256, 256>>>(ego_in, side);

        dense_kernel<<<(NTOT + 63) / 64, 128>>>(
            side, ego_in,
            W_gc + (size_t)k * 64 * 64, b_gc + (size_t)k * 64,
            W_bi + (size_t)k * 64 * 64, b_bi + (size_t)k * 64,
            ego, outs + (size_t)(k + 1) * SLICE,
            (k + 1 < NLAYERS) ? 1 : 0);

        ego_in = ego;
    }

    gather_kernel<<<(3 * BATCH * 64 + 255) / 256, 256>>>(
        users, pos_items, neg_items, (float4*)d_out);
}

// round 7
// speedup vs baseline: 1.1674x; 1.1674x over previous
#include <cuda_runtime.h>
#include <cuda_fp16.h>
#include <cstdint>
#include <cstddef>

#define N_USERS 60000
#define N_ITEMS 40000
#define NTOT    100000
#define EMB     64
#define NNZ_C   2560000
#define BATCH   4096
#define NLAYERS 3
#define ELL_CAP 128        // padded slots per row; P(deg>=128) ~ 0 for Poisson(25.6)

// Scratch (__device__ globals; no allocation allowed)
__device__ float   g_ego  [(size_t)NTOT * EMB];
__device__ __half2 g_egoh [(size_t)NTOT * (EMB / 2)];   // fp16 mirror of current ego
__device__ float   g_side [(size_t)NTOT * EMB];
__device__ float   g_outs[4][(size_t)NTOT * EMB];
__device__ float2  g_edges[(size_t)NTOT * ELL_CAP];     // (val, col-as-float-bits), ELL
__device__ int     g_deg  [NTOT];

__device__ __forceinline__ unsigned int h2_bits(__half2 v) {
    return *reinterpret_cast<unsigned int*>(&v);
}

// ---------------------------------------------------------------------------
// 1) masked ego = concat(user_emb*mask_u, item_emb*mask_i); fp32 + fp16 mirror
// ---------------------------------------------------------------------------
__global__ void init_kernel(const float4* __restrict__ ue,
                            const float4* __restrict__ ie,
                            const int* __restrict__ usz,
                            const int* __restrict__ isz,
                            float4* __restrict__ out0)
{
    int i = blockIdx.x * blockDim.x + threadIdx.x;   // NTOT * 16 float4s
    if (i >= NTOT * 16) return;
    int r = i >> 4;
    int q = i & 15;
    int c0 = q * 4;
    float4 v; int sz;
    if (r < N_USERS) { v = ue[i];                              sz = usz[r]; }
    else             { v = ie[(size_t)(r - N_USERS) * 16 + q]; sz = isz[r - N_USERS]; }
    if (c0 + 0 >= sz) v.x = 0.f;
    if (c0 + 1 >= sz) v.y = 0.f;
    if (c0 + 2 >= sz) v.z = 0.f;
    if (c0 + 3 >= sz) v.w = 0.f;
    out0[i] = v;
    uint2 h;
    h.x = h2_bits(__floats2half2_rn(v.x, v.y));
    h.y = h2_bits(__floats2half2_rn(v.z, v.w));
    *reinterpret_cast<uint2*>(g_egoh + (size_t)i * 2) = h;
}

// ---------------------------------------------------------------------------
// 2) ELL scatter: one pass, no histogram/scan. g_deg must be zeroed first.
// ---------------------------------------------------------------------------
__global__ void scatter_kernel(const float4* __restrict__ vals4,
                               const int4*   __restrict__ rows4,
                               const int4*   __restrict__ cols4)
{
    int i = blockIdx.x * blockDim.x + threadIdx.x;   // NNZ/4 threads
    if (i >= NNZ_C / 4) return;
    float4 v = vals4[i];
    int4   r = rows4[i];
    int4   c = cols4[i];

    int p;
    p = atomicAdd(&g_deg[r.x], 1); if (p < ELL_CAP) g_edges[(size_t)r.x * ELL_CAP + p] = make_float2(v.x, __int_as_float(c.x));
    p = atomicAdd(&g_deg[r.y], 1); if (p < ELL_CAP) g_edges[(size_t)r.y * ELL_CAP + p] = make_float2(v.y, __int_as_float(c.y));
    p = atomicAdd(&g_deg[r.z], 1); if (p < ELL_CAP) g_edges[(size_t)r.z * ELL_CAP + p] = make_float2(v.z, __int_as_float(c.z));
    p = atomicAdd(&g_deg[r.w], 1); if (p < ELL_CAP) g_edges[(size_t)r.w * ELL_CAP + p] = make_float2(v.w, __int_as_float(c.w));
}

// ---------------------------------------------------------------------------
// 3) ELL SpMM with fp16 gather (half the L2 traffic), fp32 accumulation.
//    16 lanes per row; each lane gathers 4 halves (8B) per edge.
// ---------------------------------------------------------------------------
__device__ __forceinline__ void accum_h(float4& acc, float wv, uint2 u)
{
    float2 f0 = __half22float2(*reinterpret_cast<const __half2*>(&u.x));
    float2 f1 = __half22float2(*reinterpret_cast<const __half2*>(&u.y));
    acc.x += wv * f0.x;
    acc.y += wv * f0.y;
    acc.z += wv * f1.x;
    acc.w += wv * f1.y;
}

__global__ void __launch_bounds__(256) spmm_kernel(float* __restrict__ side)
{
    int tid = blockIdx.x * blockDim.x + threadIdx.x;
    int r = tid >> 4;
    if (r >= NTOT) return;
    int l = tid & 15;

    int deg = g_deg[r];
    if (deg > ELL_CAP) deg = ELL_CAP;
    const float2*  ep = g_edges + (size_t)r * ELL_CAP;
    const __half2* eg = g_egoh + l * 2;   // lane offset; row stride = 32 half2

    float4 acc = make_float4(0.f, 0.f, 0.f, 0.f);

    int j = 0;
    for (; j + 8 <= deg; j += 8) {
        float4 e01 = *(const float4*)(ep + j);
        float4 e23 = *(const float4*)(ep + j + 2);
        float4 e45 = *(const float4*)(ep + j + 4);
        float4 e67 = *(const float4*)(ep + j + 6);
        uint2 x0 = *(const uint2*)(eg + (size_t)__float_as_int(e01.y) * 32);
        uint2 x1 = *(const uint2*)(eg + (size_t)__float_as_int(e01.w) * 32);
        uint2 x2 = *(const uint2*)(eg + (size_t)__float_as_int(e23.y) * 32);
        uint2 x3 = *(const uint2*)(eg + (size_t)__float_as_int(e23.w) * 32);
        uint2 x4 = *(const uint2*)(eg + (size_t)__float_as_int(e45.y) * 32);
        uint2 x5 = *(const uint2*)(eg + (size_t)__float_as_int(e45.w) * 32);
        uint2 x6 = *(const uint2*)(eg + (size_t)__float_as_int(e67.y) * 32);
        uint2 x7 = *(const uint2*)(eg + (size_t)__float_as_int(e67.w) * 32);
        accum_h(acc, e01.x, x0); accum_h(acc, e01.z, x1);
        accum_h(acc, e23.x, x2); accum_h(acc, e23.z, x3);
        accum_h(acc, e45.x, x4); accum_h(acc, e45.z, x5);
        accum_h(acc, e67.x, x6); accum_h(acc, e67.z, x7);
    }
    for (; j + 2 <= deg; j += 2) {
        float4 e01 = *(const float4*)(ep + j);
        uint2 x0 = *(const uint2*)(eg + (size_t)__float_as_int(e01.y) * 32);
        uint2 x1 = *(const uint2*)(eg + (size_t)__float_as_int(e01.w) * 32);
        accum_h(acc, e01.x, x0); accum_h(acc, e01.z, x1);
    }
    for (; j < deg; ++j) {
        float2 e = ep[j];
        uint2 x = *(const uint2*)(eg + (size_t)__float_as_int(e.y) * 32);
        accum_h(acc, e.x, x);
    }

    *(float4*)(side + (size_t)r * EMB + l * 4) = acc;
}

// ---------------------------------------------------------------------------
// 4) Fused dense layer (round-2 proven config: 256 thr, 4x4 tile):
//    pre = side@Wgc + (ego*side)@Wbi + (bgc+bbi)
//    ego_out = leaky_relu(pre) (fp32 + fp16 mirror); norm_out = normalized
// ---------------------------------------------------------------------------
__global__ void __launch_bounds__(256, 4) dense_kernel(
    const float* __restrict__ side, const float* __restrict__ ego,
    const float* __restrict__ Wgc,  const float* __restrict__ bgc,
    const float* __restrict__ Wbi,  const float* __restrict__ bbi,
    float* __restrict__ ego_out,    float* __restrict__ norm_out,
    int write_ego)
{
    __shared__ float Ash[64][64];
    __shared__ float Wsh[64][64];
    __shared__ float bsh[64];

    int t = threadIdx.x;
    int row0 = blockIdx.x * 64;
    if (t < 64) bsh[t] = bgc[t] + bbi[t];

    int tx = t & 15, ty = t >> 4;
    int c0 = tx * 4, r0 = ty * 4;

    unsigned long long acc2[4][2];
    #pragma unroll
    for (int i = 0; i < 4; ++i) { acc2[i][0] = 0ull; acc2[i][1] = 0ull; }

    #pragma unroll
    for (int half = 0; half < 2; ++half) {
        const float* W = half ? Wbi : Wgc;
        for (int i = t; i < 64 * 64; i += 256)
            Wsh[i >> 6][i & 63] = W[i];
        for (int i = t; i < 64 * 64; i += 256) {
            int m = i >> 6, j = i & 63;
            int r = row0 + m;
            float s = 0.f;
            if (r < NTOT) {
                s = side[(size_t)r * 64 + j];
                if (half) s *= ego[(size_t)r * 64 + j];
            }
            Ash[m][j] = s;
        }
        __syncthreads();

        #pragma unroll 16
        for (int k = 0; k < 64; ++k) {
            float4 bv = *(const float4*)&Wsh[k][c0];
            unsigned long long b01, b23;
            asm("mov.b64 %0, {%1,%2};" : "=l"(b01) : "f"(bv.x), "f"(bv.y));
            asm("mov.b64 %0, {%1,%2};" : "=l"(b23) : "f"(bv.z), "f"(bv.w));
            #pragma unroll
            for (int i = 0; i < 4; ++i) {
                float a = Ash[r0 + i][k];
                unsigned long long aa;
                asm("mov.b64 %0, {%1,%1};" : "=l"(aa) : "f"(a));
                asm("fma.rn.f32x2 %0, %1, %2, %0;" : "+l"(acc2[i][0]) : "l"(aa), "l"(b01));
                asm("fma.rn.f32x2 %0, %1, %2, %0;" : "+l"(acc2[i][1]) : "l"(aa), "l"(b23));
            }
        }
        __syncthreads();
    }

    #pragma unroll
    for (int i = 0; i < 4; ++i) {
        float v[4];
        asm("mov.b64 {%0,%1}, %2;" : "=f"(v[0]), "=f"(v[1]) : "l"(acc2[i][0]));
        asm("mov.b64 {%0,%1}, %2;" : "=f"(v[2]), "=f"(v[3]) : "l"(acc2[i][1]));
        float sq = 0.f;
        #pragma unroll
        for (int jj = 0; jj < 4; ++jj) {
            float x = v[jj] + bsh[c0 + jj];
            x = (x > 0.f) ? x : 0.2f * x;
            v[jj] = x;
            sq += x * x;
        }
        #pragma unroll
        for (int off = 8; off; off >>= 1)
            sq += __shfl_xor_sync(0xffffffffu, sq, off, 16);
        float inv = 1.0f / fmaxf(sqrtf(sq), 1e-12f);

        int r = row0 + r0 + i;
        if (r < NTOT) {
            float4 o = make_float4(v[0], v[1], v[2], v[3]);
            if (write_ego) {
                *(float4*)(ego_out + (size_t)r * 64 + c0) = o;
                uint2 h;
                h.x = h2_bits(__floats2half2_rn(o.x, o.y));
                h.y = h2_bits(__floats2half2_rn(o.z, o.w));
                *reinterpret_cast<uint2*>(g_egoh + (size_t)r * 32 + c0 / 2) = h;
            }
            float4 n = make_float4(o.x * inv, o.y * inv, o.z * inv, o.w * inv);
            *(float4*)(norm_out + (size_t)r * 64 + c0) = n;
        }
    }
}

// ---------------------------------------------------------------------------
// 5) Final gather
// ---------------------------------------------------------------------------
__global__ void gather_kernel(const int* __restrict__ users,
                              const int* __restrict__ pos,
                              const int* __restrict__ neg,
                              float4* __restrict__ out)
{
    int i = blockIdx.x * blockDim.x + threadIdx.x;   // 3 * BATCH * 64 float4s
    if (i >= 3 * BATCH * 64) return;
    int which = i / (BATCH * 64);
    int rem   = i - which * (BATCH * 64);
    int b  = rem >> 6;
    int q  = rem & 63;
    int slice = q >> 4;
    int qq    = q & 15;

    int row;
    if      (which == 0) row = users[b];
    else if (which == 1) row = N_USERS + pos[b];
    else                 row = N_USERS + neg[b];

    const float4* src = (const float4*)&g_outs[slice][0];
    out[i] = src[(size_t)row * 16 + qq];
}

// ---------------------------------------------------------------------------
// Launcher (graph-capturable)
// ---------------------------------------------------------------------------
extern "C" void kernel_launch(void* const* d_in, const int* in_sizes, int n_in,
                              void* d_out, int out_size)
{
    const float* user_emb   = (const float*)d_in[0];
    const float* item_emb   = (const float*)d_in[1];
    const float* W_gc       = (const float*)d_in[2];
    const float* b_gc       = (const float*)d_in[3];
    const float* W_bi       = (const float*)d_in[4];
    const float* b_bi       = (const float*)d_in[5];
    const float* adj_vals   = (const float*)d_in[6];
    const int*   adj_rows   = (const int*)d_in[7];
    const int*   adj_cols   = (const int*)d_in[8];
    const int*   user_sizes = (const int*)d_in[9];
    const int*   item_sizes = (const int*)d_in[10];
    const int*   users      = (const int*)d_in[11];
    const int*   pos_items  = (const int*)d_in[12];
    const int*   neg_items  = (const int*)d_in[13];

    float *ego, *side, *outs;
    int   *deg;
    cudaGetSymbolAddress((void**)&ego,  g_ego);
    cudaGetSymbolAddress((void**)&side, g_side);
    cudaGetSymbolAddress((void**)&outs, g_outs);
    cudaGetSymbolAddress((void**)&deg,  g_deg);

    const size_t SLICE = (size_t)NTOT * EMB;

    init_kernel<<<(NTOT * 16 + 255) / 256, 256>>>(
        (const float4*)user_emb, (const float4*)item_emb,
        user_sizes, item_sizes, (float4*)outs);

    cudaMemsetAsync(deg, 0, NTOT * sizeof(int), 0);
    scatter_kernel<<<(NNZ_C / 4 + 255) / 256, 256>>>(
        (const float4*)adj_vals, (const int4*)adj_rows, (const int4*)adj_cols);

    const float* ego_in = outs;   // g_outs[0] (fp32 view; fp16 mirror in g_egoh)
    for (int k = 0; k < NLAYERS; ++k) {
        spmm_kernel<<<(NTOT * 16 + 255) / 256, 256>>>(side);

        dense_kernel<<<(NTOT + 63) / 64, 256>>>(
            side, ego_in,
            W_gc + (size_t)k * 64 * 64, b_gc + (size_t)k * 64,
            W_bi + (size_t)k * 64 * 64, b_bi + (size_t)k * 64,
            ego, outs + (size_t)(k + 1) * SLICE,
            (k + 1 < NLAYERS) ? 1 : 0);

        ego_in = ego;
    }

    gather_kernel<<<(3 * BATCH * 64 + 255) / 256, 256>>>(
        users, pos_items, neg_items, (float4*)d_out);
}

// round 8
// speedup vs baseline: 1.3332x; 1.1420x over previous
#include <cuda_runtime.h>
#include <cuda_fp16.h>
#include <mma.h>
#include <cstdint>
#include <cstddef>

#define N_USERS 60000
#define N_ITEMS 40000
#define NTOT    100000
#define EMB     64
#define NNZ_C   2560000
#define BATCH   4096
#define NLAYERS 3
#define ELL_CAP 128        // padded slots per row; P(deg>=128) ~ 0 for Poisson(25.6)

// Scratch (__device__ globals; no allocation allowed)
__device__ float   g_ego  [(size_t)NTOT * EMB];
__device__ __half2 g_egoh [(size_t)NTOT * (EMB / 2)];   // fp16 mirror of current ego
__device__ float   g_side [(size_t)NTOT * EMB];
__device__ float   g_outs[4][(size_t)NTOT * EMB];
__device__ float2  g_edges[(size_t)NTOT * ELL_CAP];     // (val, col-as-float-bits), ELL
__device__ int     g_deg  [NTOT];

__device__ __forceinline__ unsigned int h2_bits(__half2 v) {
    return *reinterpret_cast<unsigned int*>(&v);
}

// ---------------------------------------------------------------------------
// 1) masked ego = concat(user_emb*mask_u, item_emb*mask_i); fp32 + fp16 mirror
// ---------------------------------------------------------------------------
__global__ void init_kernel(const float4* __restrict__ ue,
                            const float4* __restrict__ ie,
                            const int* __restrict__ usz,
                            const int* __restrict__ isz,
                            float4* __restrict__ out0)
{
    int i = blockIdx.x * blockDim.x + threadIdx.x;   // NTOT * 16 float4s
    if (i >= NTOT * 16) return;
    int r = i >> 4;
    int q = i & 15;
    int c0 = q * 4;
    float4 v; int sz;
    if (r < N_USERS) { v = ue[i];                              sz = usz[r]; }
    else             { v = ie[(size_t)(r - N_USERS) * 16 + q]; sz = isz[r - N_USERS]; }
    if (c0 + 0 >= sz) v.x = 0.f;
    if (c0 + 1 >= sz) v.y = 0.f;
    if (c0 + 2 >= sz) v.z = 0.f;
    if (c0 + 3 >= sz) v.w = 0.f;
    out0[i] = v;
    uint2 h;
    h.x = h2_bits(__floats2half2_rn(v.x, v.y));
    h.y = h2_bits(__floats2half2_rn(v.z, v.w));
    *reinterpret_cast<uint2*>(g_egoh + (size_t)i * 2) = h;
}

// ---------------------------------------------------------------------------
// 2) ELL scatter: one pass, no histogram/scan. g_deg must be zeroed first.
// ---------------------------------------------------------------------------
__global__ void scatter_kernel(const float4* __restrict__ vals4,
                               const int4*   __restrict__ rows4,
                               const int4*   __restrict__ cols4)
{
    int i = blockIdx.x * blockDim.x + threadIdx.x;   // NNZ/4 threads
    if (i >= NNZ_C / 4) return;
    float4 v = vals4[i];
    int4   r = rows4[i];
    int4   c = cols4[i];

    int p;
    p = atomicAdd(&g_deg[r.x], 1); if (p < ELL_CAP) g_edges[(size_t)r.x * ELL_CAP + p] = make_float2(v.x, __int_as_float(c.x));
    p = atomicAdd(&g_deg[r.y], 1); if (p < ELL_CAP) g_edges[(size_t)r.y * ELL_CAP + p] = make_float2(v.y, __int_as_float(c.y));
    p = atomicAdd(&g_deg[r.z], 1); if (p < ELL_CAP) g_edges[(size_t)r.z * ELL_CAP + p] = make_float2(v.z, __int_as_float(c.z));
    p = atomicAdd(&g_deg[r.w], 1); if (p < ELL_CAP) g_edges[(size_t)r.w * ELL_CAP + p] = make_float2(v.w, __int_as_float(c.w));
}

// ---------------------------------------------------------------------------
// 3) ELL SpMM with fp16 gather (half the L2 traffic), fp32 accumulation.
// ---------------------------------------------------------------------------
__device__ __forceinline__ void accum_h(float4& acc, float wv, uint2 u)
{
    float2 f0 = __half22float2(*reinterpret_cast<const __half2*>(&u.x));
    float2 f1 = __half22float2(*reinterpret_cast<const __half2*>(&u.y));
    acc.x += wv * f0.x;
    acc.y += wv * f0.y;
    acc.z += wv * f1.x;
    acc.w += wv * f1.y;
}

__global__ void __launch_bounds__(256) spmm_kernel(float* __restrict__ side)
{
    int tid = blockIdx.x * blockDim.x + threadIdx.x;
    int r = tid >> 4;
    if (r >= NTOT) return;
    int l = tid & 15;

    int deg = g_deg[r];
    if (deg > ELL_CAP) deg = ELL_CAP;
    const float2*  ep = g_edges + (size_t)r * ELL_CAP;
    const __half2* eg = g_egoh + l * 2;   // lane offset; row stride = 32 half2

    float4 acc = make_float4(0.f, 0.f, 0.f, 0.f);

    int j = 0;
    for (; j + 8 <= deg; j += 8) {
        float4 e01 = *(const float4*)(ep + j);
        float4 e23 = *(const float4*)(ep + j + 2);
        float4 e45 = *(const float4*)(ep + j + 4);
        float4 e67 = *(const float4*)(ep + j + 6);
        uint2 x0 = *(const uint2*)(eg + (size_t)__float_as_int(e01.y) * 32);
        uint2 x1 = *(const uint2*)(eg + (size_t)__float_as_int(e01.w) * 32);
        uint2 x2 = *(const uint2*)(eg + (size_t)__float_as_int(e23.y) * 32);
        uint2 x3 = *(const uint2*)(eg + (size_t)__float_as_int(e23.w) * 32);
        uint2 x4 = *(const uint2*)(eg + (size_t)__float_as_int(e45.y) * 32);
        uint2 x5 = *(const uint2*)(eg + (size_t)__float_as_int(e45.w) * 32);
        uint2 x6 = *(const uint2*)(eg + (size_t)__float_as_int(e67.y) * 32);
        uint2 x7 = *(const uint2*)(eg + (size_t)__float_as_int(e67.w) * 32);
        accum_h(acc, e01.x, x0); accum_h(acc, e01.z, x1);
        accum_h(acc, e23.x, x2); accum_h(acc, e23.z, x3);
        accum_h(acc, e45.x, x4); accum_h(acc, e45.z, x5);
        accum_h(acc, e67.x, x6); accum_h(acc, e67.z, x7);
    }
    for (; j + 2 <= deg; j += 2) {
        float4 e01 = *(const float4*)(ep + j);
        uint2 x0 = *(const uint2*)(eg + (size_t)__float_as_int(e01.y) * 32);
        uint2 x1 = *(const uint2*)(eg + (size_t)__float_as_int(e01.w) * 32);
        accum_h(acc, e01.x, x0); accum_h(acc, e01.z, x1);
    }
    for (; j < deg; ++j) {
        float2 e = ep[j];
        uint2 x = *(const uint2*)(eg + (size_t)__float_as_int(e.y) * 32);
        accum_h(acc, e.x, x);
    }

    *(float4*)(side + (size_t)r * EMB + l * 4) = acc;
}

// ---------------------------------------------------------------------------
// 4) Fused dense layer on tensor cores (HMMA fp16 in / fp32 accum):
//    A' = [side | ego*side] (64x128 fp16), W' = [Wgc ; Wbi] (128x64 fp16)
//    C = A' @ W'; ego_out = leaky_relu(C + b); norm_out = row-normalized
//    256 threads = 8 warps; each warp owns 2 of the 16 16x16 output tiles.
// ---------------------------------------------------------------------------
#define A_LD   136   // 128 + 8 halves
#define W_LD   72    // 64 + 8 halves
#define A_BYTES (64 * A_LD * 2)     // 17408
#define W_BYTES (128 * W_LD * 2)    // 18432

__global__ void __launch_bounds__(256) dense_kernel(
    const float* __restrict__ side, const float* __restrict__ ego,
    const float* __restrict__ Wgc,  const float* __restrict__ bgc,
    const float* __restrict__ Wbi,  const float* __restrict__ bbi,
    float* __restrict__ ego_out,    float* __restrict__ norm_out,
    int write_ego)
{
    using namespace nvcuda;

    __shared__ __align__(16) char smembuf[A_BYTES + W_BYTES];
    __shared__ float bsh[64];

    __half* Ah  = reinterpret_cast<__half*>(smembuf);             // 64 x A_LD
    __half* Wsh = reinterpret_cast<__half*>(smembuf + A_BYTES);   // 128 x W_LD
    float*  Csh = reinterpret_cast<float*>(smembuf);              // 64 x 64 (aliases Ah)

    int t = threadIdx.x;
    int row0 = blockIdx.x * 64;
    if (t < 64) bsh[t] = bgc[t] + bbi[t];

    // Stage W' = [Wgc ; Wbi] as fp16 (128 x 64)
    for (int i = t; i < 128 * 64; i += 256) {
        int k = i >> 6, n = i & 63;
        float w = (k < 64) ? Wgc[k * 64 + n] : Wbi[(k - 64) * 64 + n];
        Wsh[k * W_LD + n] = __float2half_rn(w);
    }
    // Stage A' = [side | ego*side] as fp16 (64 x 128)
    for (int i = t; i < 64 * 64; i += 256) {
        int m = i >> 6, k = i & 63;
        int r = row0 + m;
        float s = 0.f, e = 0.f;
        if (r < NTOT) {
            s = side[(size_t)r * 64 + k];
            e = ego [(size_t)r * 64 + k];
        }
        Ah[m * A_LD + k]      = __float2half_rn(s);
        Ah[m * A_LD + 64 + k] = __float2half_rn(s * e);
    }
    __syncthreads();

    // MMA: 16 tiles (4x4 grid of 16x16); warp w owns tiles 2w, 2w+1 (same row)
    int warp = t >> 5;
    int tr = warp >> 1;                 // tile row 0..3
    int tc0 = (warp & 1) * 2;           // tile cols {0,1} or {2,3}

    wmma::fragment<wmma::accumulator, 16, 16, 16, float> c0, c1;
    wmma::fill_fragment(c0, 0.f);
    wmma::fill_fragment(c1, 0.f);

    #pragma unroll
    for (int kk = 0; kk < 8; ++kk) {
        wmma::fragment<wmma::matrix_a, 16, 16, 16, __half, wmma::row_major> a;
        wmma::fragment<wmma::matrix_b, 16, 16, 16, __half, wmma::row_major> b0, b1;
        wmma::load_matrix_sync(a, Ah + (tr * 16) * A_LD + kk * 16, A_LD);
        wmma::load_matrix_sync(b0, Wsh + (kk * 16) * W_LD + tc0 * 16, W_LD);
        wmma::load_matrix_sync(b1, Wsh + (kk * 16) * W_LD + (tc0 + 1) * 16, W_LD);
        wmma::mma_sync(c0, a, b0, c0);
        wmma::mma_sync(c1, a, b1, c1);
    }
    __syncthreads();   // all A reads done before Csh overwrites Ah

    wmma::store_matrix_sync(Csh + (tr * 16) * 64 + tc0 * 16,       c0, 64, wmma::mem_row_major);
    wmma::store_matrix_sync(Csh + (tr * 16) * 64 + (tc0 + 1) * 16, c1, 64, wmma::mem_row_major);
    __syncthreads();

    // Epilogue: bias + leaky relu + row L2-norm; thread -> 4x4 chunk
    int tx = t & 15, ty = t >> 4;
    int c0i = tx * 4, r0 = ty * 4;

    #pragma unroll
    for (int i = 0; i < 4; ++i) {
        float v[4];
        #pragma unroll
        for (int jj = 0; jj < 4; ++jj) {
            float x = Csh[(r0 + i) * 64 + c0i + jj] + bsh[c0i + jj];
            x = (x > 0.f) ? x : 0.2f * x;
            v[jj] = x;
        }
        float sq = v[0]*v[0] + v[1]*v[1] + v[2]*v[2] + v[3]*v[3];
        #pragma unroll
        for (int off = 8; off; off >>= 1)
            sq += __shfl_xor_sync(0xffffffffu, sq, off, 16);
        float inv = 1.0f / fmaxf(sqrtf(sq), 1e-12f);

        int r = row0 + r0 + i;
        if (r < NTOT) {
            float4 o = make_float4(v[0], v[1], v[2], v[3]);
            if (write_ego) {
                *(float4*)(ego_out + (size_t)r * 64 + c0i) = o;
                uint2 h;
                h.x = h2_bits(__floats2half2_rn(o.x, o.y));
                h.y = h2_bits(__floats2half2_rn(o.z, o.w));
                *reinterpret_cast<uint2*>(g_egoh + (size_t)r * 32 + c0i / 2) = h;
            }
            float4 n = make_float4(o.x * inv, o.y * inv, o.z * inv, o.w * inv);
            *(float4*)(norm_out + (size_t)r * 64 + c0i) = n;
        }
    }
}

// ---------------------------------------------------------------------------
// 5) Final gather
// ---------------------------------------------------------------------------
__global__ void gather_kernel(const int* __restrict__ users,
                              const int* __restrict__ pos,
                              const int* __restrict__ neg,
                              float4* __restrict__ out)
{
    int i = blockIdx.x * blockDim.x + threadIdx.x;   // 3 * BATCH * 64 float4s
    if (i >= 3 * BATCH * 64) return;
    int which = i / (BATCH * 64);
    int rem   = i - which * (BATCH * 64);
    int b  = rem >> 6;
    int q  = rem & 63;
    int slice = q >> 4;
    int qq    = q & 15;

    int row;
    if      (which == 0) row = users[b];
    else if (which == 1) row = N_USERS + pos[b];
    else                 row = N_USERS + neg[b];

    const float4* src = (const float4*)&g_outs[slice][0];
    out[i] = src[(size_t)row * 16 + qq];
}

// ---------------------------------------------------------------------------
// Launcher (graph-capturable)
// ---------------------------------------------------------------------------
extern "C" void kernel_launch(void* const* d_in, const int* in_sizes, int n_in,
                              void* d_out, int out_size)
{
    const float* user_emb   = (const float*)d_in[0];
    const float* item_emb   = (const float*)d_in[1];
    const float* W_gc       = (const float*)d_in[2];
    const float* b_gc       = (const float*)d_in[3];
    const float* W_bi       = (const float*)d_in[4];
    const float* b_bi       = (const float*)d_in[5];
    const float* adj_vals   = (const float*)d_in[6];
    const int*   adj_rows   = (const int*)d_in[7];
    const int*   adj_cols   = (const int*)d_in[8];
    const int*   user_sizes = (const int*)d_in[9];
    const int*   item_sizes = (const int*)d_in[10];
    const int*   users      = (const int*)d_in[11];
    const int*   pos_items  = (const int*)d_in[12];
    const int*   neg_items  = (const int*)d_in[13];

    float *ego, *side, *outs;
    int   *deg;
    cudaGetSymbolAddress((void**)&ego,  g_ego);
    cudaGetSymbolAddress((void**)&side, g_side);
    cudaGetSymbolAddress((void**)&outs, g_outs);
    cudaGetSymbolAddress((void**)&deg,  g_deg);

    const size_t SLICE = (size_t)NTOT * EMB;

    init_kernel<<<(NTOT * 16 + 255) / 256, 256>>>(
        (const float4*)user_emb, (const float4*)item_emb,
        user_sizes, item_sizes, (float4*)outs);

    cudaMemsetAsync(deg, 0, NTOT * sizeof(int), 0);
    scatter_kernel<<<(NNZ_C / 4 + 255) / 256, 256>>>(
        (const float4*)adj_vals, (const int4*)adj_rows, (const int4*)adj_cols);

    const float* ego_in = outs;   // g_outs[0] (fp32 view; fp16 mirror in g_egoh)
    for (int k = 0; k < NLAYERS; ++k) {
        spmm_kernel<<<(NTOT * 16 + 255) / 256, 256>>>(side);

        dense_kernel<<<(NTOT + 63) / 64, 256>>>(
            side, ego_in,
            W_gc + (size_t)k * 64 * 64, b_gc + (size_t)k * 64,
            W_bi + (size_t)k * 64 * 64, b_bi + (size_t)k * 64,
            ego, outs + (size_t)(k + 1) * SLICE,
            (k + 1 < NLAYERS) ? 1 : 0);

        ego_in = ego;
    }

    gather_kernel<<<(3 * BATCH * 64 + 255) / 256, 256>>>(
        users, pos_items, neg_items, (float4*)d_out);
}

// round 10
// speedup vs baseline: 1.5539x; 1.1655x over previous
#include <cuda_runtime.h>
#include <cuda_fp16.h>
#include <mma.h>
#include <cstdint>
#include <cstddef>

#define N_USERS 60000
#define N_ITEMS 40000
#define NTOT    100000
#define EMB     64
#define NNZ_C   2560000
#define BATCH   4096
#define NLAYERS 3
#define ELL_CAP 128        // padded slots per row; P(deg>=128) ~ 0 for Poisson(25.6)

// Scratch (__device__ globals; no allocation allowed)
__device__ __half2 g_egoh [(size_t)NTOT * (EMB / 2)];   // fp16 current ego
__device__ __half  g_a    [(size_t)NTOT * 128];         // A' = [side | side*ego] fp16
__device__ float   g_outs[4][(size_t)NTOT * EMB];
__device__ float2  g_edges[(size_t)NTOT * ELL_CAP];     // (val, col-as-float-bits), ELL
__device__ int     g_deg  [NTOT];
__device__ __half  g_wh [NLAYERS * 128 * 64];           // W' = [Wgc;Wbi] fp16 per layer
__device__ float   g_bs [NLAYERS * 64];                 // bgc + bbi per layer

__device__ __forceinline__ unsigned int h2_bits(__half2 v) {
    return *reinterpret_cast<unsigned int*>(&v);
}

// ---------------------------------------------------------------------------
// 0) One-time weight conversion: W' fp16 + summed bias
// ---------------------------------------------------------------------------
__global__ void prep_w_kernel(const float* __restrict__ Wgc,
                              const float* __restrict__ Wbi,
                              const float* __restrict__ bgc,
                              const float* __restrict__ bbi)
{
    int i = blockIdx.x * blockDim.x + threadIdx.x;
    if (i < NLAYERS * 128 * 64) {
        int k = i / 8192, rem = i - k * 8192;
        int kk = rem >> 6, n = rem & 63;
        float w = (kk < 64) ? Wgc[k * 4096 + kk * 64 + n]
                            : Wbi[k * 4096 + (kk - 64) * 64 + n];
        g_wh[i] = __float2half_rn(w);
    }
    if (i < NLAYERS * 64)
        g_bs[i] = bgc[i] + bbi[i];
}

// ---------------------------------------------------------------------------
// 1) masked ego = concat(user_emb*mask_u, item_emb*mask_i); fp32 out0 + fp16
// ---------------------------------------------------------------------------
__global__ void init_kernel(const float4* __restrict__ ue,
                            const float4* __restrict__ ie,
                            const int* __restrict__ usz,
                            const int* __restrict__ isz,
                            float4* __restrict__ out0)
{
    int i = blockIdx.x * blockDim.x + threadIdx.x;   // NTOT * 16 float4s
    if (i >= NTOT * 16) return;
    int r = i >> 4;
    int q = i & 15;
    int c0 = q * 4;
    float4 v; int sz;
    if (r < N_USERS) { v = ue[i];                              sz = usz[r]; }
    else             { v = ie[(size_t)(r - N_USERS) * 16 + q]; sz = isz[r - N_USERS]; }
    if (c0 + 0 >= sz) v.x = 0.f;
    if (c0 + 1 >= sz) v.y = 0.f;
    if (c0 + 2 >= sz) v.z = 0.f;
    if (c0 + 3 >= sz) v.w = 0.f;
    out0[i] = v;
    uint2 h;
    h.x = h2_bits(__floats2half2_rn(v.x, v.y));
    h.y = h2_bits(__floats2half2_rn(v.z, v.w));
    *reinterpret_cast<uint2*>(g_egoh + (size_t)i * 2) = h;
}

// ---------------------------------------------------------------------------
// 2) ELL scatter: one pass, no histogram/scan. g_deg must be zeroed first.
// ---------------------------------------------------------------------------
__global__ void scatter_kernel(const float4* __restrict__ vals4,
                               const int4*   __restrict__ rows4,
                               const int4*   __restrict__ cols4)
{
    int i = blockIdx.x * blockDim.x + threadIdx.x;   // NNZ/4 threads
    if (i >= NNZ_C / 4) return;
    float4 v = vals4[i];
    int4   r = rows4[i];
    int4   c = cols4[i];

    int p;
    p = atomicAdd(&g_deg[r.x], 1); if (p < ELL_CAP) g_edges[(size_t)r.x * ELL_CAP + p] = make_float2(v.x, __int_as_float(c.x));
    p = atomicAdd(&g_deg[r.y], 1); if (p < ELL_CAP) g_edges[(size_t)r.y * ELL_CAP + p] = make_float2(v.y, __int_as_float(c.y));
    p = atomicAdd(&g_deg[r.z], 1); if (p < ELL_CAP) g_edges[(size_t)r.z * ELL_CAP + p] = make_float2(v.z, __int_as_float(c.z));
    p = atomicAdd(&g_deg[r.w], 1); if (p < ELL_CAP) g_edges[(size_t)r.w * ELL_CAP + p] = make_float2(v.w, __int_as_float(c.w));
}

// ---------------------------------------------------------------------------
// 3) ELL SpMM (fp16 gather, fp32 accum) fused with A' emission:
//    writes g_a[r] = [side_fp16 | (side*ego)_fp16]   (256 B/row)
// ---------------------------------------------------------------------------
__device__ __forceinline__ void accum_h(float4& acc, float wv, uint2 u)
{
    float2 f0 = __half22float2(*reinterpret_cast<const __half2*>(&u.x));
    float2 f1 = __half22float2(*reinterpret_cast<const __half2*>(&u.y));
    acc.x += wv * f0.x;
    acc.y += wv * f0.y;
    acc.z += wv * f1.x;
    acc.w += wv * f1.y;
}

__global__ void __launch_bounds__(256) spmm_kernel()
{
    int tid = blockIdx.x * blockDim.x + threadIdx.x;
    int r = tid >> 4;
    if (r >= NTOT) return;
    int l = tid & 15;

    int deg = g_deg[r];
    if (deg > ELL_CAP) deg = ELL_CAP;
    const float2*  ep = g_edges + (size_t)r * ELL_CAP;
    const __half2* eg = g_egoh + l * 2;   // lane offset; row stride = 32 half2

    float4 acc = make_float4(0.f, 0.f, 0.f, 0.f);

    int j = 0;
    for (; j + 8 <= deg; j += 8) {
        float4 e01 = *(const float4*)(ep + j);
        float4 e23 = *(const float4*)(ep + j + 2);
        float4 e45 = *(const float4*)(ep + j + 4);
        float4 e67 = *(const float4*)(ep + j + 6);
        uint2 x0 = *(const uint2*)(eg + (size_t)__float_as_int(e01.y) * 32);
        uint2 x1 = *(const uint2*)(eg + (size_t)__float_as_int(e01.w) * 32);
        uint2 x2 = *(const uint2*)(eg + (size_t)__float_as_int(e23.y) * 32);
        uint2 x3 = *(const uint2*)(eg + (size_t)__float_as_int(e23.w) * 32);
        uint2 x4 = *(const uint2*)(eg + (size_t)__float_as_int(e45.y) * 32);
        uint2 x5 = *(const uint2*)(eg + (size_t)__float_as_int(e45.w) * 32);
        uint2 x6 = *(const uint2*)(eg + (size_t)__float_as_int(e67.y) * 32);
        uint2 x7 = *(const uint2*)(eg + (size_t)__float_as_int(e67.w) * 32);
        accum_h(acc, e01.x, x0); accum_h(acc, e01.z, x1);
        accum_h(acc, e23.x, x2); accum_h(acc, e23.z, x3);
        accum_h(acc, e45.x, x4); accum_h(acc, e45.z, x5);
        accum_h(acc, e67.x, x6); accum_h(acc, e67.z, x7);
    }
    for (; j + 2 <= deg; j += 2) {
        float4 e01 = *(const float4*)(ep + j);
        uint2 x0 = *(const uint2*)(eg + (size_t)__float_as_int(e01.y) * 32);
        uint2 x1 = *(const uint2*)(eg + (size_t)__float_as_int(e01.w) * 32);
        accum_h(acc, e01.x, x0); accum_h(acc, e01.z, x1);
    }
    for (; j < deg; ++j) {
        float2 e = ep[j];
        uint2 x = *(const uint2*)(eg + (size_t)__float_as_int(e.y) * 32);
        accum_h(acc, e.x, x);
    }

    // own ego (fp16) for the bilinear product
    uint2 eh = *reinterpret_cast<const uint2*>(g_egoh + (size_t)r * 32 + l * 2);
    float2 g0 = __half22float2(*reinterpret_cast<const __half2*>(&eh.x));
    float2 g1 = __half22float2(*reinterpret_cast<const __half2*>(&eh.y));

    uint2 s, p;
    s.x = h2_bits(__floats2half2_rn(acc.x, acc.y));
    s.y = h2_bits(__floats2half2_rn(acc.z, acc.w));
    p.x = h2_bits(__floats2half2_rn(acc.x * g0.x, acc.y * g0.y));
    p.y = h2_bits(__floats2half2_rn(acc.z * g1.x, acc.w * g1.y));

    __half* arow = g_a + (size_t)r * 128;
    *reinterpret_cast<uint2*>(arow + l * 4)      = s;
    *reinterpret_cast<uint2*>(arow + 64 + l * 4) = p;
}

// ---------------------------------------------------------------------------
// 4) Dense layer: WMMA on pre-packed fp16 A' and W'. Staging = pure copies.
// ---------------------------------------------------------------------------
#define A_LD   136   // 128 + 8 halves (272 B rows)
#define W_LD   72    // 64 + 8 halves  (144 B rows; 144 = 9*16 -> uint4-aligned)
#define A_BYTES (64 * A_LD * 2)     // 17408
#define W_BYTES (128 * W_LD * 2)    // 18432

__global__ void __launch_bounds__(256) dense_kernel(
    const __half* __restrict__ Wh,  const float* __restrict__ bias,
    float* __restrict__ norm_out,   int write_ego)
{
    using namespace nvcuda;

    __shared__ __align__(16) char smembuf[A_BYTES + W_BYTES];
    __shared__ float bsh[64];

    __half* Ah  = reinterpret_cast<__half*>(smembuf);             // 64 x A_LD
    __half* Wsh = reinterpret_cast<__half*>(smembuf + A_BYTES);   // 128 x W_LD
    float*  Csh = reinterpret_cast<float*>(smembuf);              // 64 x 64 (aliases Ah)

    int t = threadIdx.x;
    int row0 = blockIdx.x * 64;
    if (t < 64) bsh[t] = bias[t];

    // Stage W': 128x64 halves = 8192 halves = 1024 uint4; 4 per thread.
    // k = idx>>3 (8 uint4 per 64-half row), q = idx&7.
    {
        const uint4* src = reinterpret_cast<const uint4*>(Wh);
        #pragma unroll
        for (int jj = 0; jj < 4; ++jj) {
            int idx = t + jj * 256;
            int k = idx >> 3, q = idx & 7;
            *reinterpret_cast<uint4*>(Wsh + k * W_LD + q * 8) = src[idx];
        }
    }
    // Stage A': 64 rows x 16 uint4 = 1024 uint4; 4 per thread.
    {
        #pragma unroll
        for (int jj = 0; jj < 4; ++jj) {
            int idx = t + jj * 256;
            int m = idx >> 4, q = idx & 15;
            int r = row0 + m;
            uint4 v = make_uint4(0u, 0u, 0u, 0u);
            if (r < NTOT)
                v = *reinterpret_cast<const uint4*>(g_a + (size_t)r * 128 + q * 8);
            *reinterpret_cast<uint4*>(Ah + m * A_LD + q * 8) = v;
        }
    }
    __syncthreads();

    // MMA: 16 tiles (4x4 of 16x16); warp w owns tiles 2w, 2w+1 (same tile row)
    int warp = t >> 5;
    int tr = warp >> 1;
    int tc0 = (warp & 1) * 2;

    wmma::fragment<wmma::accumulator, 16, 16, 16, float> c0, c1;
    wmma::fill_fragment(c0, 0.f);
    wmma::fill_fragment(c1, 0.f);

    #pragma unroll
    for (int kk = 0; kk < 8; ++kk) {
        wmma::fragment<wmma::matrix_a, 16, 16, 16, __half, wmma::row_major> a;
        wmma::fragment<wmma::matrix_b, 16, 16, 16, __half, wmma::row_major> b0, b1;
        wmma::load_matrix_sync(a, Ah + (tr * 16) * A_LD + kk * 16, A_LD);
        wmma::load_matrix_sync(b0, Wsh + (kk * 16) * W_LD + tc0 * 16, W_LD);
        wmma::load_matrix_sync(b1, Wsh + (kk * 16) * W_LD + (tc0 + 1) * 16, W_LD);
        wmma::mma_sync(c0, a, b0, c0);
        wmma::mma_sync(c1, a, b1, c1);
    }
    __syncthreads();   // all A reads done before Csh overwrites Ah

    wmma::store_matrix_sync(Csh + (tr * 16) * 64 + tc0 * 16,       c0, 64, wmma::mem_row_major);
    wmma::store_matrix_sync(Csh + (tr * 16) * 64 + (tc0 + 1) * 16, c1, 64, wmma::mem_row_major);
    __syncthreads();

    // Epilogue: bias + leaky relu + row L2-norm; thread -> 4x4 chunk
    int tx = t & 15, ty = t >> 4;
    int c0i = tx * 4, r0 = ty * 4;

    #pragma unroll
    for (int i = 0; i < 4; ++i) {
        float v[4];
        #pragma unroll
        for (int jj = 0; jj < 4; ++jj) {
            float x = Csh[(r0 + i) * 64 + c0i + jj] + bsh[c0i + jj];
            x = (x > 0.f) ? x : 0.2f * x;
            v[jj] = x;
        }
        float sq = v[0]*v[0] + v[1]*v[1] + v[2]*v[2] + v[3]*v[3];
        #pragma unroll
        for (int off = 8; off; off >>= 1)
            sq += __shfl_xor_sync(0xffffffffu, sq, off, 16);
        float inv = 1.0f / fmaxf(sqrtf(sq), 1e-12f);

        int r = row0 + r0 + i;
        if (r < NTOT) {
            if (write_ego) {
                uint2 h;
                h.x = h2_bits(__floats2half2_rn(v[0], v[1]));
                h.y = h2_bits(__floats2half2_rn(v[2], v[3]));
                *reinterpret_cast<uint2*>(g_egoh + (size_t)r * 32 + c0i / 2) = h;
            }
            float4 n = make_float4(v[0] * inv, v[1] * inv, v[2] * inv, v[3] * inv);
            *(float4*)(norm_out + (size_t)r * 64 + c0i) = n;
        }
    }
}

// ---------------------------------------------------------------------------
// 5) Final gather
// ---------------------------------------------------------------------------
__global__ void gather_kernel(const int* __restrict__ users,
                              const int* __restrict__ pos,
                              const int* __restrict__ neg,
                              float4* __restrict__ out)
{
    int i = blockIdx.x * blockDim.x + threadIdx.x;   // 3 * BATCH * 64 float4s
    if (i >= 3 * BATCH * 64) return;
    int which = i / (BATCH * 64);
    int rem   = i - which * (BATCH * 64);
    int b  = rem >> 6;
    int q  = rem & 63;
    int slice = q >> 4;
    int qq    = q & 15;

    int row;
    if      (which == 0) row = users[b];
    else if (which == 1) row = N_USERS + pos[b];
    else                 row = N_USERS + neg[b];

    const float4* src = (const float4*)&g_outs[slice][0];
    out[i] = src[(size_t)row * 16 + qq];
}

// ---------------------------------------------------------------------------
// Launcher (graph-capturable)
// ---------------------------------------------------------------------------
extern "C" void kernel_launch(void* const* d_in, const int* in_sizes, int n_in,
                              void* d_out, int out_size)
{
    const float* user_emb   = (const float*)d_in[0];
    const float* item_emb   = (const float*)d_in[1];
    const float* W_gc       = (const float*)d_in[2];
    const float* b_gc       = (const float*)d_in[3];
    const float* W_bi       = (const float*)d_in[4];
    const float* b_bi       = (const float*)d_in[5];
    const float* adj_vals   = (const float*)d_in[6];
    const int*   adj_rows   = (const int*)d_in[7];
    const int*   adj_cols   = (const int*)d_in[8];
    const int*   user_sizes = (const int*)d_in[9];
    const int*   item_sizes = (const int*)d_in[10];
    const int*   users      = (const int*)d_in[11];
    const int*   pos_items  = (const int*)d_in[12];
    const int*   neg_items  = (const int*)d_in[13];

    float *outs;
    int   *deg;
    __half *wh;
    float *bs;
    cudaGetSymbolAddress((void**)&outs, g_outs);
    cudaGetSymbolAddress((void**)&deg,  g_deg);
    cudaGetSymbolAddress((void**)&wh,   g_wh);
    cudaGetSymbolAddress((void**)&bs,   g_bs);

    const size_t SLICE = (size_t)NTOT * EMB;

    prep_w_kernel<<<(NLAYERS * 128 * 64 + 255) / 256, 256>>>(W_gc, W_bi, b_gc, b_bi);

    init_kernel<<<(NTOT * 16 + 255) / 256, 256>>>(
        (const float4*)user_emb, (const float4*)item_emb,
        user_sizes, item_sizes, (float4*)outs);

    cudaMemsetAsync(deg, 0, NTOT * sizeof(int), 0);
    scatter_kernel<<<(NNZ_C / 4 + 255) / 256, 256>>>(
        (const float4*)adj_vals, (const int4*)adj_rows, (const int4*)adj_cols);

    for (int k = 0; k < NLAYERS; ++k) {
        spmm_kernel<<<(NTOT * 16 + 255) / 256, 256>>>();

        dense_kernel<<<(NTOT + 63) / 64, 256>>>(
            wh + (size_t)k * 128 * 64, bs + (size_t)k * 64,
            outs + (size_t)(k + 1) * SLICE,
            (k + 1 < NLAYERS) ? 1 : 0);
    }

    gather_kernel<<<(3 * BATCH * 64 + 255) / 256, 256>>>(
        users, pos_items, neg_items, (float4*)d_out);
}

// round 11
// speedup vs baseline: 1.6161x; 1.0400x over previous
#include <cuda_runtime.h>
#include <cuda_fp16.h>
#include <mma.h>
#include <cstdint>
#include <cstddef>

#define N_USERS 60000
#define N_ITEMS 40000
#define NTOT    100000
#define EMB     64
#define NNZ_C   2560000
#define BATCH   4096
#define NLAYERS 3
#define ELL_CAP 128        // padded slots per row; P(deg>=128) ~ 0 for Poisson(25.6)

#define ROWS_PB 32         // rows per block in the fused layer kernel
#define LTHREADS 512       // 32 rows x 16 lanes

// Scratch (__device__ globals; no allocation allowed)
__device__ __half2 g_egoh[2][(size_t)NTOT * (EMB / 2)]; // ping-pong fp16 ego
__device__ float   g_outs[4][(size_t)NTOT * EMB];
__device__ float2  g_edges[(size_t)NTOT * ELL_CAP];     // (val, col-as-float-bits), ELL
__device__ int     g_deg  [NTOT];
__device__ __half  g_wh [NLAYERS * 128 * 64];           // W' = [Wgc;Wbi] fp16 per layer
__device__ float   g_bs [NLAYERS * 64];                 // bgc + bbi per layer

__device__ __forceinline__ unsigned int h2_bits(__half2 v) {
    return *reinterpret_cast<unsigned int*>(&v);
}

// ---------------------------------------------------------------------------
// 0) One-time weight conversion: W' fp16 + summed bias
// ---------------------------------------------------------------------------
__global__ void prep_w_kernel(const float* __restrict__ Wgc,
                              const float* __restrict__ Wbi,
                              const float* __restrict__ bgc,
                              const float* __restrict__ bbi)
{
    int i = blockIdx.x * blockDim.x + threadIdx.x;
    if (i < NLAYERS * 128 * 64) {
        int k = i / 8192, rem = i - k * 8192;
        int kk = rem >> 6, n = rem & 63;
        float w = (kk < 64) ? Wgc[k * 4096 + kk * 64 + n]
                            : Wbi[k * 4096 + (kk - 64) * 64 + n];
        g_wh[i] = __float2half_rn(w);
    }
    if (i < NLAYERS * 64)
        g_bs[i] = bgc[i] + bbi[i];
}

// ---------------------------------------------------------------------------
// 1) masked ego = concat(user_emb*mask_u, item_emb*mask_i); fp32 out0 + fp16
// ---------------------------------------------------------------------------
__global__ void init_kernel(const float4* __restrict__ ue,
                            const float4* __restrict__ ie,
                            const int* __restrict__ usz,
                            const int* __restrict__ isz,
                            float4* __restrict__ out0)
{
    int i = blockIdx.x * blockDim.x + threadIdx.x;   // NTOT * 16 float4s
    if (i >= NTOT * 16) return;
    int r = i >> 4;
    int q = i & 15;
    int c0 = q * 4;
    float4 v; int sz;
    if (r < N_USERS) { v = ue[i];                              sz = usz[r]; }
    else             { v = ie[(size_t)(r - N_USERS) * 16 + q]; sz = isz[r - N_USERS]; }
    if (c0 + 0 >= sz) v.x = 0.f;
    if (c0 + 1 >= sz) v.y = 0.f;
    if (c0 + 2 >= sz) v.z = 0.f;
    if (c0 + 3 >= sz) v.w = 0.f;
    out0[i] = v;
    uint2 h;
    h.x = h2_bits(__floats2half2_rn(v.x, v.y));
    h.y = h2_bits(__floats2half2_rn(v.z, v.w));
    *reinterpret_cast<uint2*>(&g_egoh[0][(size_t)i * 2]) = h;
}

// ---------------------------------------------------------------------------
// 2) ELL scatter: one pass, no histogram/scan. g_deg must be zeroed first.
// ---------------------------------------------------------------------------
__global__ void scatter_kernel(const float4* __restrict__ vals4,
                               const int4*   __restrict__ rows4,
                               const int4*   __restrict__ cols4)
{
    int i = blockIdx.x * blockDim.x + threadIdx.x;   // NNZ/4 threads
    if (i >= NNZ_C / 4) return;
    float4 v = vals4[i];
    int4   r = rows4[i];
    int4   c = cols4[i];

    int p;
    p = atomicAdd(&g_deg[r.x], 1); if (p < ELL_CAP) g_edges[(size_t)r.x * ELL_CAP + p] = make_float2(v.x, __int_as_float(c.x));
    p = atomicAdd(&g_deg[r.y], 1); if (p < ELL_CAP) g_edges[(size_t)r.y * ELL_CAP + p] = make_float2(v.y, __int_as_float(c.y));
    p = atomicAdd(&g_deg[r.z], 1); if (p < ELL_CAP) g_edges[(size_t)r.z * ELL_CAP + p] = make_float2(v.z, __int_as_float(c.z));
    p = atomicAdd(&g_deg[r.w], 1); if (p < ELL_CAP) g_edges[(size_t)r.w * ELL_CAP + p] = make_float2(v.w, __int_as_float(c.w));
}

// ---------------------------------------------------------------------------
// 3) Fused layer kernel: ELL SpMM (fp16 gather, fp32 accum) -> A' in shared
//    -> WMMA (32x64 out, K=128) -> bias/leakyReLU/row-norm epilogue.
//    Block: 512 threads = 32 rows x 16 lanes = 16 warps (warps 0-7 do MMA).
// ---------------------------------------------------------------------------
__device__ __forceinline__ void accum_h(float4& acc, float wv, uint2 u)
{
    float2 f0 = __half22float2(*reinterpret_cast<const __half2*>(&u.x));
    float2 f1 = __half22float2(*reinterpret_cast<const __half2*>(&u.y));
    acc.x += wv * f0.x;
    acc.y += wv * f0.y;
    acc.z += wv * f1.x;
    acc.w += wv * f1.y;
}

#define A_LD   136   // 128 + 8 halves
#define W_LD   72    // 64 + 8 halves
#define A_BYTES (ROWS_PB * A_LD * 2)   // 8704
#define W_BYTES (128 * W_LD * 2)       // 18432

__global__ void __launch_bounds__(LTHREADS) layer_kernel(
    const __half*  __restrict__ Wh,     const float* __restrict__ bias,
    const __half2* __restrict__ ego_in, __half2* __restrict__ ego_out,
    float* __restrict__ norm_out,       int write_ego)
{
    using namespace nvcuda;

    __shared__ __align__(32) char smembuf[A_BYTES + W_BYTES];
    __shared__ float bsh[64];

    __half* Ah  = reinterpret_cast<__half*>(smembuf);             // 32 x A_LD
    __half* Wsh = reinterpret_cast<__half*>(smembuf + A_BYTES);   // 128 x W_LD
    float*  Csh = reinterpret_cast<float*>(smembuf);              // 32 x 64 (aliases Ah)

    int t = threadIdx.x;
    int row0 = blockIdx.x * ROWS_PB;
    if (t < 64) bsh[t] = bias[t];

    // Stage W': 8192 halves = 1024 uint4; 2 per thread.
    {
        const uint4* src = reinterpret_cast<const uint4*>(Wh);
        #pragma unroll
        for (int jj = 0; jj < 2; ++jj) {
            int idx = t + jj * LTHREADS;
            int k = idx >> 3, q = idx & 7;
            *reinterpret_cast<uint4*>(Wsh + k * W_LD + q * 8) = src[idx];
        }
    }

    // ---- SpMM phase: warp w -> rows row0+2w (lanes 0-15), row0+2w+1 (16-31)
    int warp = t >> 5, lane = t & 31;
    int m = warp * 2 + (lane >> 4);
    int l = lane & 15;
    int r = row0 + m;

    float4 acc = make_float4(0.f, 0.f, 0.f, 0.f);
    float2 g0 = make_float2(0.f, 0.f), g1 = make_float2(0.f, 0.f);

    if (r < NTOT) {
        int deg = g_deg[r];
        if (deg > ELL_CAP) deg = ELL_CAP;
        const float2*  ep = g_edges + (size_t)r * ELL_CAP;
        const __half2* eg = ego_in + l * 2;   // lane offset; row stride 32 half2

        int j = 0;
        for (; j + 8 <= deg; j += 8) {
            float4 e01 = *(const float4*)(ep + j);
            float4 e23 = *(const float4*)(ep + j + 2);
            float4 e45 = *(const float4*)(ep + j + 4);
            float4 e67 = *(const float4*)(ep + j + 6);
            uint2 x0 = *(const uint2*)(eg + (size_t)__float_as_int(e01.y) * 32);
            uint2 x1 = *(const uint2*)(eg + (size_t)__float_as_int(e01.w) * 32);
            uint2 x2 = *(const uint2*)(eg + (size_t)__float_as_int(e23.y) * 32);
            uint2 x3 = *(const uint2*)(eg + (size_t)__float_as_int(e23.w) * 32);
            uint2 x4 = *(const uint2*)(eg + (size_t)__float_as_int(e45.y) * 32);
            uint2 x5 = *(const uint2*)(eg + (size_t)__float_as_int(e45.w) * 32);
            uint2 x6 = *(const uint2*)(eg + (size_t)__float_as_int(e67.y) * 32);
            uint2 x7 = *(const uint2*)(eg + (size_t)__float_as_int(e67.w) * 32);
            accum_h(acc, e01.x, x0); accum_h(acc, e01.z, x1);
            accum_h(acc, e23.x, x2); accum_h(acc, e23.z, x3);
            accum_h(acc, e45.x, x4); accum_h(acc, e45.z, x5);
            accum_h(acc, e67.x, x6); accum_h(acc, e67.z, x7);
        }
        for (; j + 2 <= deg; j += 2) {
            float4 e01 = *(const float4*)(ep + j);
            uint2 x0 = *(const uint2*)(eg + (size_t)__float_as_int(e01.y) * 32);
            uint2 x1 = *(const uint2*)(eg + (size_t)__float_as_int(e01.w) * 32);
            accum_h(acc, e01.x, x0); accum_h(acc, e01.z, x1);
        }
        for (; j < deg; ++j) {
            float2 e = ep[j];
            uint2 x = *(const uint2*)(eg + (size_t)__float_as_int(e.y) * 32);
            accum_h(acc, e.x, x);
        }

        uint2 eh = *reinterpret_cast<const uint2*>(ego_in + (size_t)r * 32 + l * 2);
        g0 = __half22float2(*reinterpret_cast<const __half2*>(&eh.x));
        g1 = __half22float2(*reinterpret_cast<const __half2*>(&eh.y));
    }

    // A' row -> shared (fp16): [side | side*ego]
    {
        uint2 s, p;
        s.x = h2_bits(__floats2half2_rn(acc.x, acc.y));
        s.y = h2_bits(__floats2half2_rn(acc.z, acc.w));
        p.x = h2_bits(__floats2half2_rn(acc.x * g0.x, acc.y * g0.y));
        p.y = h2_bits(__floats2half2_rn(acc.z * g1.x, acc.w * g1.y));
        *reinterpret_cast<uint2*>(Ah + m * A_LD + l * 4)      = s;
        *reinterpret_cast<uint2*>(Ah + m * A_LD + 64 + l * 4) = p;
    }
    __syncthreads();

    // ---- MMA phase: C (32x64) = 2x4 tiles of 16x16; warps 0-7, one tile each
    wmma::fragment<wmma::accumulator, 16, 16, 16, float> cfrag;
    int tr = (warp >> 2) & 1, tc = warp & 3;
    if (warp < 8) {
        wmma::fill_fragment(cfrag, 0.f);
        #pragma unroll
        for (int kk = 0; kk < 8; ++kk) {
            wmma::fragment<wmma::matrix_a, 16, 16, 16, __half, wmma::row_major> a;
            wmma::fragment<wmma::matrix_b, 16, 16, 16, __half, wmma::row_major> b;
            wmma::load_matrix_sync(a, Ah + (tr * 16) * A_LD + kk * 16, A_LD);
            wmma::load_matrix_sync(b, Wsh + (kk * 16) * W_LD + tc * 16, W_LD);
            wmma::mma_sync(cfrag, a, b, cfrag);
        }
    }
    __syncthreads();   // all A reads done before Csh overwrites Ah
    if (warp < 8)
        wmma::store_matrix_sync(Csh + (tr * 16) * 64 + tc * 16, cfrag, 64,
                                wmma::mem_row_major);
    __syncthreads();

    // ---- Epilogue: 512 threads; thread -> (row ty, 4-col chunk tx)
    int ty = t >> 4, tx = t & 15;
    int c0i = tx * 4;

    float v[4];
    #pragma unroll
    for (int jj = 0; jj < 4; ++jj) {
        float x = Csh[ty * 64 + c0i + jj] + bsh[c0i + jj];
        x = (x > 0.f) ? x : 0.2f * x;
        v[jj] = x;
    }
    float sq = v[0]*v[0] + v[1]*v[1] + v[2]*v[2] + v[3]*v[3];
    #pragma unroll
    for (int off = 8; off; off >>= 1)
        sq += __shfl_xor_sync(0xffffffffu, sq, off, 16);
    float inv = 1.0f / fmaxf(sqrtf(sq), 1e-12f);

    int rr = row0 + ty;
    if (rr < NTOT) {
        if (write_ego) {
            uint2 h;
            h.x = h2_bits(__floats2half2_rn(v[0], v[1]));
            h.y = h2_bits(__floats2half2_rn(v[2], v[3]));
            *reinterpret_cast<uint2*>(ego_out + (size_t)rr * 32 + c0i / 2) = h;
        }
        float4 n = make_float4(v[0] * inv, v[1] * inv, v[2] * inv, v[3] * inv);
        *(float4*)(norm_out + (size_t)rr * 64 + c0i) = n;
    }
}

// ---------------------------------------------------------------------------
// 4) Final gather
// ---------------------------------------------------------------------------
__global__ void gather_kernel(const int* __restrict__ users,
                              const int* __restrict__ pos,
                              const int* __restrict__ neg,
                              float4* __restrict__ out)
{
    int i = blockIdx.x * blockDim.x + threadIdx.x;   // 3 * BATCH * 64 float4s
    if (i >= 3 * BATCH * 64) return;
    int which = i / (BATCH * 64);
    int rem   = i - which * (BATCH * 64);
    int b  = rem >> 6;
    int q  = rem & 63;
    int slice = q >> 4;
    int qq    = q & 15;

    int row;
    if      (which == 0) row = users[b];
    else if (which == 1) row = N_USERS + pos[b];
    else                 row = N_USERS + neg[b];

    const float4* src = (const float4*)&g_outs[slice][0];
    out[i] = src[(size_t)row * 16 + qq];
}

// ---------------------------------------------------------------------------
// Launcher (graph-capturable)
// ---------------------------------------------------------------------------
extern "C" void kernel_launch(void* const* d_in, const int* in_sizes, int n_in,
                              void* d_out, int out_size)
{
    const float* user_emb   = (const float*)d_in[0];
    const float* item_emb   = (const float*)d_in[1];
    const float* W_gc       = (const float*)d_in[2];
    const float* b_gc       = (const float*)d_in[3];
    const float* W_bi       = (const float*)d_in[4];
    const float* b_bi       = (const float*)d_in[5];
    const float* adj_vals   = (const float*)d_in[6];
    const int*   adj_rows   = (const int*)d_in[7];
    const int*   adj_cols   = (const int*)d_in[8];
    const int*   user_sizes = (const int*)d_in[9];
    const int*   item_sizes = (const int*)d_in[10];
    const int*   users      = (const int*)d_in[11];
    const int*   pos_items  = (const int*)d_in[12];
    const int*   neg_items  = (const int*)d_in[13];

    float *outs;
    int   *deg;
    __half *wh;
    float *bs;
    __half2 *egoh;
    cudaGetSymbolAddress((void**)&outs, g_outs);
    cudaGetSymbolAddress((void**)&deg,  g_deg);
    cudaGetSymbolAddress((void**)&wh,   g_wh);
    cudaGetSymbolAddress((void**)&bs,   g_bs);
    cudaGetSymbolAddress((void**)&egoh, g_egoh);

    const size_t SLICE  = (size_t)NTOT * EMB;
    const size_t HSLICE = (size_t)NTOT * (EMB / 2);

    prep_w_kernel<<<(NLAYERS * 128 * 64 + 255) / 256, 256>>>(W_gc, W_bi, b_gc, b_bi);

    init_kernel<<<(NTOT * 16 + 255) / 256, 256>>>(
        (const float4*)user_emb, (const float4*)item_emb,
        user_sizes, item_sizes, (float4*)outs);

    cudaMemsetAsync(deg, 0, NTOT * sizeof(int), 0);
    scatter_kernel<<<(NNZ_C / 4 + 255) / 256, 256>>>(
        (const float4*)adj_vals, (const int4*)adj_rows, (const int4*)adj_cols);

    int cur = 0;
    for (int k = 0; k < NLAYERS; ++k) {
        layer_kernel<<<(NTOT + ROWS_PB - 1) / ROWS_PB, LTHREADS>>>(
            wh + (size_t)k * 128 * 64, bs + (size_t)k * 64,
            egoh + (size_t)cur * HSLICE, egoh + (size_t)(1 - cur) * HSLICE,
            outs + (size_t)(k + 1) * SLICE,
            (k + 1 < NLAYERS) ? 1 : 0);
        cur ^= 1;
    }

    gather_kernel<<<(3 * BATCH * 64 + 255) / 256, 256>>>(
        users, pos_items, neg_items, (float4*)d_out);
}

// round 12
// speedup vs baseline: 1.6586x; 1.0263x over previous
#include <cuda_runtime.h>
#include <cuda_fp16.h>
#include <mma.h>
#include <cstdint>
#include <cstddef>

#define N_USERS 60000
#define N_ITEMS 40000
#define NTOT    100000
#define EMB     64
#define NNZ_C   2560000
#define BATCH   4096
#define NLAYERS 3
#define ELL_CAP 128        // padded slots per row; P(deg>=128) ~ 0 for Poisson(25.6)

#define ROWS_PB 32         // rows per block in the fused layer kernel
#define LTHREADS 512       // 32 rows x 16 lanes

// Scratch (__device__ globals; no allocation allowed)
__device__ __half2 g_egoh[2][(size_t)NTOT * (EMB / 2)]; // ping-pong fp16 ego
__device__ float   g_outs[4][(size_t)NTOT * EMB];
__device__ float2  g_edges[(size_t)NTOT * ELL_CAP];     // (w as half2-bits, col), ELL
__device__ int     g_deg  [NTOT];
__device__ __half  g_wh [NLAYERS * 128 * 64];           // W' = [Wgc;Wbi] fp16 per layer
__device__ float   g_bs [NLAYERS * 64];                 // bgc + bbi per layer

__device__ __forceinline__ unsigned int h2_bits(__half2 v) {
    return *reinterpret_cast<unsigned int*>(&v);
}
__device__ __forceinline__ __half2 bits_h2(unsigned int b) {
    return *reinterpret_cast<__half2*>(&b);
}

// ---------------------------------------------------------------------------
// 0) One-time weight conversion: W' fp16 + summed bias
// ---------------------------------------------------------------------------
__global__ void prep_w_kernel(const float* __restrict__ Wgc,
                              const float* __restrict__ Wbi,
                              const float* __restrict__ bgc,
                              const float* __restrict__ bbi)
{
    int i = blockIdx.x * blockDim.x + threadIdx.x;
    if (i < NLAYERS * 128 * 64) {
        int k = i / 8192, rem = i - k * 8192;
        int kk = rem >> 6, n = rem & 63;
        float w = (kk < 64) ? Wgc[k * 4096 + kk * 64 + n]
                            : Wbi[k * 4096 + (kk - 64) * 64 + n];
        g_wh[i] = __float2half_rn(w);
    }
    if (i < NLAYERS * 64)
        g_bs[i] = bgc[i] + bbi[i];
}

// ---------------------------------------------------------------------------
// 1) masked ego = concat(user_emb*mask_u, item_emb*mask_i); fp32 out0 + fp16
// ---------------------------------------------------------------------------
__global__ void init_kernel(const float4* __restrict__ ue,
                            const float4* __restrict__ ie,
                            const int* __restrict__ usz,
                            const int* __restrict__ isz,
                            float4* __restrict__ out0)
{
    int i = blockIdx.x * blockDim.x + threadIdx.x;   // NTOT * 16 float4s
    if (i >= NTOT * 16) return;
    int r = i >> 4;
    int q = i & 15;
    int c0 = q * 4;
    float4 v; int sz;
    if (r < N_USERS) { v = ue[i];                              sz = usz[r]; }
    else             { v = ie[(size_t)(r - N_USERS) * 16 + q]; sz = isz[r - N_USERS]; }
    if (c0 + 0 >= sz) v.x = 0.f;
    if (c0 + 1 >= sz) v.y = 0.f;
    if (c0 + 2 >= sz) v.z = 0.f;
    if (c0 + 3 >= sz) v.w = 0.f;
    out0[i] = v;
    uint2 h;
    h.x = h2_bits(__floats2half2_rn(v.x, v.y));
    h.y = h2_bits(__floats2half2_rn(v.z, v.w));
    *reinterpret_cast<uint2*>(&g_egoh[0][(size_t)i * 2]) = h;
}

// ---------------------------------------------------------------------------
// 2) ELL scatter; edge record = (w as broadcast half2 bits, col bits)
// ---------------------------------------------------------------------------
__global__ void scatter_kernel(const float4* __restrict__ vals4,
                               const int4*   __restrict__ rows4,
                               const int4*   __restrict__ cols4)
{
    int i = blockIdx.x * blockDim.x + threadIdx.x;   // NNZ/4 threads
    if (i >= NNZ_C / 4) return;
    float4 v = vals4[i];
    int4   r = rows4[i];
    int4   c = cols4[i];

    #define PUT(vv, rr, cc) do {                                              \
        int p = atomicAdd(&g_deg[rr], 1);                                     \
        if (p < ELL_CAP) {                                                    \
            unsigned int wb = h2_bits(__float2half2_rn(vv));                  \
            g_edges[(size_t)(rr) * ELL_CAP + p] =                             \
                make_float2(__uint_as_float(wb), __int_as_float(cc));         \
        }                                                                     \
    } while (0)
    PUT(v.x, r.x, c.x);
    PUT(v.y, r.y, c.y);
    PUT(v.z, r.z, c.z);
    PUT(v.w, r.w, c.w);
    #undef PUT
}

// ---------------------------------------------------------------------------
// 3) Fused layer kernel: ELL SpMM (fp16 gather, HFMA2 chunk accum, fp32 flush)
//    -> A' in shared -> WMMA (32x64 out, K=128) -> bias/leakyReLU/norm.
//    Block: 512 threads = 32 rows x 16 lanes = 16 warps (warps 0-7 do MMA).
// ---------------------------------------------------------------------------
__device__ __forceinline__ void accum_f(float4& acc, float wv, uint2 u)
{
    float2 f0 = __half22float2(bits_h2(u.x));
    float2 f1 = __half22float2(bits_h2(u.y));
    acc.x += wv * f0.x;
    acc.y += wv * f0.y;
    acc.z += wv * f1.x;
    acc.w += wv * f1.y;
}

#define A_LD   136   // 128 + 8 halves
#define W_LD   72    // 64 + 8 halves
#define A_BYTES (ROWS_PB * A_LD * 2)   // 8704
#define W_BYTES (128 * W_LD * 2)       // 18432

__global__ void __launch_bounds__(LTHREADS) layer_kernel(
    const __half*  __restrict__ Wh,     const float* __restrict__ bias,
    const __half2* __restrict__ ego_in, __half2* __restrict__ ego_out,
    float* __restrict__ norm_out,       int write_ego)
{
    using namespace nvcuda;

    __shared__ __align__(32) char smembuf[A_BYTES + W_BYTES];
    __shared__ float bsh[64];

    __half* Ah  = reinterpret_cast<__half*>(smembuf);             // 32 x A_LD
    __half* Wsh = reinterpret_cast<__half*>(smembuf + A_BYTES);   // 128 x W_LD
    float*  Csh = reinterpret_cast<float*>(smembuf);              // 32 x 64 (aliases Ah)

    int t = threadIdx.x;
    int row0 = blockIdx.x * ROWS_PB;
    if (t < 64) bsh[t] = bias[t];

    // Stage W': 8192 halves = 1024 uint4; 2 per thread.
    {
        const uint4* src = reinterpret_cast<const uint4*>(Wh);
        #pragma unroll
        for (int jj = 0; jj < 2; ++jj) {
            int idx = t + jj * LTHREADS;
            int k = idx >> 3, q = idx & 7;
            *reinterpret_cast<uint4*>(Wsh + k * W_LD + q * 8) = src[idx];
        }
    }

    // ---- SpMM phase: warp w -> rows row0+2w (lanes 0-15), row0+2w+1 (16-31)
    int warp = t >> 5, lane = t & 31;
    int m = warp * 2 + (lane >> 4);
    int l = lane & 15;
    int r = row0 + m;

    float4 acc = make_float4(0.f, 0.f, 0.f, 0.f);
    float2 g0 = make_float2(0.f, 0.f), g1 = make_float2(0.f, 0.f);

    if (r < NTOT) {
        int deg = g_deg[r];
        if (deg > ELL_CAP) deg = ELL_CAP;
        const float2*  ep = g_edges + (size_t)r * ELL_CAP;
        const __half2* eg = ego_in + l * 2;   // lane offset; row stride 32 half2

        int j = 0;
        for (; j + 8 <= deg; j += 8) {
            float4 e01 = *(const float4*)(ep + j);
            float4 e23 = *(const float4*)(ep + j + 2);
            float4 e45 = *(const float4*)(ep + j + 4);
            float4 e67 = *(const float4*)(ep + j + 6);
            uint2 x0 = *(const uint2*)(eg + (size_t)__float_as_int(e01.y) * 32);
            uint2 x1 = *(const uint2*)(eg + (size_t)__float_as_int(e01.w) * 32);
            uint2 x2 = *(const uint2*)(eg + (size_t)__float_as_int(e23.y) * 32);
            uint2 x3 = *(const uint2*)(eg + (size_t)__float_as_int(e23.w) * 32);
            uint2 x4 = *(const uint2*)(eg + (size_t)__float_as_int(e45.y) * 32);
            uint2 x5 = *(const uint2*)(eg + (size_t)__float_as_int(e45.w) * 32);
            uint2 x6 = *(const uint2*)(eg + (size_t)__float_as_int(e67.y) * 32);
            uint2 x7 = *(const uint2*)(eg + (size_t)__float_as_int(e67.w) * 32);

            // fp16 chunk accumulation (2 HFMA2 per edge), fp32 flush per chunk
            __half2 a0 = bits_h2(0u), a1 = bits_h2(0u);
            __half2 w;
            w = bits_h2(__float_as_uint(e01.x));
            a0 = __hfma2(w, bits_h2(x0.x), a0); a1 = __hfma2(w, bits_h2(x0.y), a1);
            w = bits_h2(__float_as_uint(e01.z));
            a0 = __hfma2(w, bits_h2(x1.x), a0); a1 = __hfma2(w, bits_h2(x1.y), a1);
            w = bits_h2(__float_as_uint(e23.x));
            a0 = __hfma2(w, bits_h2(x2.x), a0); a1 = __hfma2(w, bits_h2(x2.y), a1);
            w = bits_h2(__float_as_uint(e23.z));
            a0 = __hfma2(w, bits_h2(x3.x), a0); a1 = __hfma2(w, bits_h2(x3.y), a1);
            w = bits_h2(__float_as_uint(e45.x));
            a0 = __hfma2(w, bits_h2(x4.x), a0); a1 = __hfma2(w, bits_h2(x4.y), a1);
            w = bits_h2(__float_as_uint(e45.z));
            a0 = __hfma2(w, bits_h2(x5.x), a0); a1 = __hfma2(w, bits_h2(x5.y), a1);
            w = bits_h2(__float_as_uint(e67.x));
            a0 = __hfma2(w, bits_h2(x6.x), a0); a1 = __hfma2(w, bits_h2(x6.y), a1);
            w = bits_h2(__float_as_uint(e67.z));
            a0 = __hfma2(w, bits_h2(x7.x), a0); a1 = __hfma2(w, bits_h2(x7.y), a1);

            float2 f0 = __half22float2(a0);
            float2 f1 = __half22float2(a1);
            acc.x += f0.x; acc.y += f0.y; acc.z += f1.x; acc.w += f1.y;
        }
        for (; j + 2 <= deg; j += 2) {      // fp32 tail (exact path)
            float4 e01 = *(const float4*)(ep + j);
            uint2 x0 = *(const uint2*)(eg + (size_t)__float_as_int(e01.y) * 32);
            uint2 x1 = *(const uint2*)(eg + (size_t)__float_as_int(e01.w) * 32);
            accum_f(acc, __low2float(bits_h2(__float_as_uint(e01.x))), x0);
            accum_f(acc, __low2float(bits_h2(__float_as_uint(e01.z))), x1);
        }
        for (; j < deg; ++j) {
            float2 e = ep[j];
            uint2 x = *(const uint2*)(eg + (size_t)__float_as_int(e.y) * 32);
            accum_f(acc, __low2float(bits_h2(__float_as_uint(e.x))), x);
        }

        uint2 eh = *reinterpret_cast<const uint2*>(ego_in + (size_t)r * 32 + l * 2);
        g0 = __half22float2(bits_h2(eh.x));
        g1 = __half22float2(bits_h2(eh.y));
    }

    // A' row -> shared (fp16): [side | side*ego]
    {
        uint2 s, p;
        s.x = h2_bits(__floats2half2_rn(acc.x, acc.y));
        s.y = h2_bits(__floats2half2_rn(acc.z, acc.w));
        p.x = h2_bits(__floats2half2_rn(acc.x * g0.x, acc.y * g0.y));
        p.y = h2_bits(__floats2half2_rn(acc.z * g1.x, acc.w * g1.y));
        *reinterpret_cast<uint2*>(Ah + m * A_LD + l * 4)      = s;
        *reinterpret_cast<uint2*>(Ah + m * A_LD + 64 + l * 4) = p;
    }
    __syncthreads();

    // ---- MMA phase: C (32x64) = 2x4 tiles of 16x16; warps 0-7, one tile each
    wmma::fragment<wmma::accumulator, 16, 16, 16, float> cfrag;
    int tr = (warp >> 2) & 1, tc = warp & 3;
    if (warp < 8) {
        wmma::fill_fragment(cfrag, 0.f);
        #pragma unroll
        for (int kk = 0; kk < 8; ++kk) {
            wmma::fragment<wmma::matrix_a, 16, 16, 16, __half, wmma::row_major> a;
            wmma::fragment<wmma::matrix_b, 16, 16, 16, __half, wmma::row_major> b;
            wmma::load_matrix_sync(a, Ah + (tr * 16) * A_LD + kk * 16, A_LD);
            wmma::load_matrix_sync(b, Wsh + (kk * 16) * W_LD + tc * 16, W_LD);
            wmma::mma_sync(cfrag, a, b, cfrag);
        }
    }
    __syncthreads();   // all A reads done before Csh overwrites Ah
    if (warp < 8)
        wmma::store_matrix_sync(Csh + (tr * 16) * 64 + tc * 16, cfrag, 64,
                                wmma::mem_row_major);
    __syncthreads();

    // ---- Epilogue: 512 threads; thread -> (row ty, 4-col chunk tx)
    int ty = t >> 4, tx = t & 15;
    int c0i = tx * 4;

    float v[4];
    #pragma unroll
    for (int jj = 0; jj < 4; ++jj) {
        float x = Csh[ty * 64 + c0i + jj] + bsh[c0i + jj];
        x = (x > 0.f) ? x : 0.2f * x;
        v[jj] = x;
    }
    float sq = v[0]*v[0] + v[1]*v[1] + v[2]*v[2] + v[3]*v[3];
    #pragma unroll
    for (int off = 8; off; off >>= 1)
        sq += __shfl_xor_sync(0xffffffffu, sq, off, 16);
    float inv = 1.0f / fmaxf(sqrtf(sq), 1e-12f);

    int rr = row0 + ty;
    if (rr < NTOT) {
        if (write_ego) {
            uint2 h;
            h.x = h2_bits(__floats2half2_rn(v[0], v[1]));
            h.y = h2_bits(__floats2half2_rn(v[2], v[3]));
            *reinterpret_cast<uint2*>(ego_out + (size_t)rr * 32 + c0i / 2) = h;
        }
        float4 n = make_float4(v[0] * inv, v[1] * inv, v[2] * inv, v[3] * inv);
        *(float4*)(norm_out + (size_t)rr * 64 + c0i) = n;
    }
}

// ---------------------------------------------------------------------------
// 4) Final gather
// ---------------------------------------------------------------------------
__global__ void gather_kernel(const int* __restrict__ users,
                              const int* __restrict__ pos,
                              const int* __restrict__ neg,
                              float4* __restrict__ out)
{
    int i = blockIdx.x * blockDim.x + threadIdx.x;   // 3 * BATCH * 64 float4s
    if (i >= 3 * BATCH * 64) return;
    int which = i / (BATCH * 64);
    int rem   = i - which * (BATCH * 64);
    int b  = rem >> 6;
    int q  = rem & 63;
    int slice = q >> 4;
    int qq    = q & 15;

    int row;
    if      (which == 0) row = users[b];
    else if (which == 1) row = N_USERS + pos[b];
    else                 row = N_USERS + neg[b];

    const float4* src = (const float4*)&g_outs[slice][0];
    out[i] = src[(size_t)row * 16 + qq];
}

// ---------------------------------------------------------------------------
// Launcher (graph-capturable)
// ---------------------------------------------------------------------------
extern "C" void kernel_launch(void* const* d_in, const int* in_sizes, int n_in,
                              void* d_out, int out_size)
{
    const float* user_emb   = (const float*)d_in[0];
    const float* item_emb   = (const float*)d_in[1];
    const float* W_gc       = (const float*)d_in[2];
    const float* b_gc       = (const float*)d_in[3];
    const float* W_bi       = (const float*)d_in[4];
    const float* b_bi       = (const float*)d_in[5];
    const float* adj_vals   = (const float*)d_in[6];
    const int*   adj_rows   = (const int*)d_in[7];
    const int*   adj_cols   = (const int*)d_in[8];
    const int*   user_sizes = (const int*)d_in[9];
    const int*   item_sizes = (const int*)d_in[10];
    const int*   users      = (const int*)d_in[11];
    const int*   pos_items  = (const int*)d_in[12];
    const int*   neg_items  = (const int*)d_in[13];

    float *outs;
    int   *deg;
    __half *wh;
    float *bs;
    __half2 *egoh;
    cudaGetSymbolAddress((void**)&outs, g_outs);
    cudaGetSymbolAddress((void**)&deg,  g_deg);
    cudaGetSymbolAddress((void**)&wh,   g_wh);
    cudaGetSymbolAddress((void**)&bs,   g_bs);
    cudaGetSymbolAddress((void**)&egoh, g_egoh);

    const size_t SLICE  = (size_t)NTOT * EMB;
    const size_t HSLICE = (size_t)NTOT * (EMB / 2);

    prep_w_kernel<<<(NLAYERS * 128 * 64 + 255) / 256, 256>>>(W_gc, W_bi, b_gc, b_bi);

    init_kernel<<<(NTOT * 16 + 255) / 256, 256>>>(
        (const float4*)user_emb, (const float4*)item_emb,
        user_sizes, item_sizes, (float4*)outs);

    cudaMemsetAsync(deg, 0, NTOT * sizeof(int), 0);
    scatter_kernel<<<(NNZ_C / 4 + 255) / 256, 256>>>(
        (const float4*)adj_vals, (const int4*)adj_rows, (const int4*)adj_cols);

    int cur = 0;
    for (int k = 0; k < NLAYERS; ++k) {
        layer_kernel<<<(NTOT + ROWS_PB - 1) / ROWS_PB, LTHREADS>>>(
            wh + (size_t)k * 128 * 64, bs + (size_t)k * 64,
            egoh + (size_t)cur * HSLICE, egoh + (size_t)(1 - cur) * HSLICE,
            outs + (size_t)(k + 1) * SLICE,
            (k + 1 < NLAYERS) ? 1 : 0);
        cur ^= 1;
    }

    gather_kernel<<<(3 * BATCH * 64 + 255) / 256, 256>>>(
        users, pos_items, neg_items, (float4*)d_out);
}